// round 1
// baseline (speedup 1.0000x reference)
#include <cuda_runtime.h>
#include <math.h>

#define NTOK 8192
#define NE   8
#define DDIM 1024
#define HDIM 5632
#define CAP  1280
#define BK   16

#define OUT_Y    0
#define OUT_AUX  8388608
#define OUT_TOP  (8388608 + 1)
#define OUT_KEEP (8388608 + 1 + NTOK)

// ---------------- scratch (static device globals; no runtime alloc) --------
__device__ __align__(256) float d_probs[NTOK * NE];
__device__ __align__(256) float d_z2[NTOK];
__device__ int   d_top[NTOK];
__device__ int   d_keep[NTOK];
__device__ int   d_slot[NTOK];
__device__ int   d_gidx[NE * CAP];
__device__ int   d_counts[NE];
__device__ int   d_counts_cap[NE];
__device__ __align__(256) float d_xe[(size_t)NE * CAP * DDIM];   //  40 MB
__device__ __align__(256) float d_h [(size_t)NE * CAP * HDIM];   // 231 MB
__device__ __align__(256) float d_ye[(size_t)NE * CAP * DDIM];   //  40 MB

// ---------------- 1. router: logits, softmax, argmax, z --------------------
__global__ void router_kernel(const float* __restrict__ x,
                              const float* __restrict__ Wg)
{
    __shared__ float sWg[NE * DDIM];
    int t = threadIdx.x;
    for (int i = t; i < NE * DDIM; i += 256) sWg[i] = Wg[i];
    __syncthreads();

    int warp = t >> 5, lane = t & 31;
    int tok  = blockIdx.x * 8 + warp;
    const float* xr = x + (size_t)tok * DDIM;

    float acc[NE];
#pragma unroll
    for (int e = 0; e < NE; e++) acc[e] = 0.f;
    for (int k = lane; k < DDIM; k += 32) {
        float xv = xr[k];
#pragma unroll
        for (int e = 0; e < NE; e++) acc[e] = fmaf(xv, sWg[e * DDIM + k], acc[e]);
    }
#pragma unroll
    for (int e = 0; e < NE; e++) {
#pragma unroll
        for (int o = 16; o > 0; o >>= 1)
            acc[e] += __shfl_down_sync(0xffffffffu, acc[e], o);
    }
    if (lane == 0) {
        float m = acc[0]; int am = 0;
#pragma unroll
        for (int e = 1; e < NE; e++) if (acc[e] > m) { m = acc[e]; am = e; }
        float p[NE]; float s = 0.f;
#pragma unroll
        for (int e = 0; e < NE; e++) { p[e] = expf(acc[e] - m); s += p[e]; }
        float inv = 1.f / s;
#pragma unroll
        for (int e = 0; e < NE; e++) d_probs[tok * NE + e] = p[e] * inv;
        float z = m + logf(s);
        d_z2[tok] = z * z;
        d_top[tok] = am;
    }
}

// ------- 2. ordered per-expert position scan (deterministic, 1 block) ------
__global__ void scan_kernel()
{
    __shared__ unsigned long long s0[1024], s1[1024];
    __shared__ int base[NE];
    int t = threadIdx.x;
    if (t < NE) base[t] = 0;
    __syncthreads();

    for (int tile = 0; tile < NTOK / 1024; tile++) {
        int i = tile * 1024 + t;
        int e = d_top[i];
        unsigned long long v0 = (e < 4)  ? (1ULL << (16 * e))       : 0ULL;
        unsigned long long v1 = (e >= 4) ? (1ULL << (16 * (e - 4))) : 0ULL;
        s0[t] = v0; s1[t] = v1;
        __syncthreads();
        for (int off = 1; off < 1024; off <<= 1) {
            unsigned long long a0 = (t >= off) ? s0[t - off] : 0ULL;
            unsigned long long a1 = (t >= off) ? s1[t - off] : 0ULL;
            __syncthreads();
            s0[t] += a0; s1[t] += a1;
            __syncthreads();
        }
        unsigned long long w = (e < 4) ? s0[t] : s1[t];
        int sh   = 16 * (e & 3);
        int posl = (int)((w >> sh) & 0xFFFFULL) - 1;   // exclusive within tile
        int pos  = base[e] + posl;
        int kp   = (pos < CAP) ? 1 : 0;
        d_keep[i] = kp;
        d_slot[i] = kp ? pos : (CAP - 1);
        if (kp) d_gidx[e * CAP + pos] = i;
        __syncthreads();
        if (t < 4)      base[t] += (int)((s0[1023] >> (16 * t)) & 0xFFFFULL);
        else if (t < 8) base[t] += (int)((s1[1023] >> (16 * (t - 4))) & 0xFFFFULL);
        __syncthreads();
    }
    if (t < NE) {
        d_counts[t] = base[t];
        d_counts_cap[t] = base[t] < CAP ? base[t] : CAP;
    }
}

// ------- 3. deterministic aux-loss reduction --------------------------------
__global__ void reduce_kernel(float* __restrict__ out_aux)
{
    __shared__ float sm[1024];
    __shared__ float pe[NE];
    int t = threadIdx.x;
    float pp[NE];
#pragma unroll
    for (int e = 0; e < NE; e++) pp[e] = 0.f;
    float zz = 0.f;
    for (int i = t; i < NTOK; i += 1024) {
#pragma unroll
        for (int e = 0; e < NE; e++) pp[e] += d_probs[i * NE + e];
        zz += d_z2[i];
    }
#pragma unroll
    for (int e = 0; e < NE; e++) {
        sm[t] = pp[e]; __syncthreads();
        for (int o = 512; o > 0; o >>= 1) {
            if (t < o) sm[t] += sm[t + o];
            __syncthreads();
        }
        if (t == 0) pe[e] = sm[0];
        __syncthreads();
    }
    sm[t] = zz; __syncthreads();
    for (int o = 512; o > 0; o >>= 1) {
        if (t < o) sm[t] += sm[t + o];
        __syncthreads();
    }
    if (t == 0) {
        float bal = 0.f;
        for (int e = 0; e < NE; e++)
            bal += (pe[e] / (float)NTOK) * ((float)d_counts[e] / (float)NTOK);
        bal *= 0.01f * (float)NE;            // AUX_W * E
        out_aux[0] = bal + (sm[0] / (float)NTOK) * 0.001f;   // + Z_W * mean(z^2)
    }
}

// ------- 4. gather tokens into expert/capacity buffer -----------------------
__global__ void gather_kernel(const float* __restrict__ x)
{
    int b = blockIdx.x;               // e*CAP + slot
    int e = b / CAP, s = b % CAP;
    if (s >= d_counts_cap[e]) return; // unused slot: output never read
    int i = d_gidx[b];
    const float4* src = (const float4*)(x + (size_t)i * DDIM);
    float4* dst = (float4*)(d_xe + (size_t)b * DDIM);
    int t = threadIdx.x;              // 128 threads, 256 float4 per row
    dst[t]       = src[t];
    dst[t + 128] = src[t + 128];
}

// ------- 5. GEMM1 fused SiLU: h = silu(xe@Wg^T) * (xe@Wu^T) ------------------
// block tile: M=128 rows x 64 h-cols (dual accumulators for g and u halves)
__global__ __launch_bounds__(256)
void gemm1_kernel(const float* __restrict__ W13)
{
    __shared__ float As[BK][132];
    __shared__ float Bg[BK][68];
    __shared__ float Bu[BK][68];

    int e  = blockIdx.z;
    int m0 = blockIdx.y * 128;
    int n0 = blockIdx.x * 64;
    int t  = threadIdx.x;
    int tx = t & 15, ty = t >> 4;

    const float* Abase = d_xe + (size_t)e * CAP * DDIM;
    const float* Wbase = W13 + (size_t)e * 2 * HDIM * DDIM;

    float accg[8][4], accu[8][4];
#pragma unroll
    for (int i = 0; i < 8; i++)
#pragma unroll
        for (int j = 0; j < 4; j++) { accg[i][j] = 0.f; accu[i][j] = 0.f; }

    int bcol = t >> 2, bkq = (t & 3) << 2;

    for (int kt = 0; kt < DDIM / BK; kt++) {
        int k0 = kt * BK;
#pragma unroll
        for (int q = t; q < 512; q += 256) {
            int row = q >> 2, kq = (q & 3) << 2;
            float4 v = *(const float4*)(Abase + (size_t)(m0 + row) * DDIM + k0 + kq);
            As[kq + 0][row] = v.x; As[kq + 1][row] = v.y;
            As[kq + 2][row] = v.z; As[kq + 3][row] = v.w;
        }
        {
            float4 vg = *(const float4*)(Wbase + (size_t)(n0 + bcol) * DDIM + k0 + bkq);
            float4 vu = *(const float4*)(Wbase + (size_t)(HDIM + n0 + bcol) * DDIM + k0 + bkq);
            Bg[bkq + 0][bcol] = vg.x; Bg[bkq + 1][bcol] = vg.y;
            Bg[bkq + 2][bcol] = vg.z; Bg[bkq + 3][bcol] = vg.w;
            Bu[bkq + 0][bcol] = vu.x; Bu[bkq + 1][bcol] = vu.y;
            Bu[bkq + 2][bcol] = vu.z; Bu[bkq + 3][bcol] = vu.w;
        }
        __syncthreads();
#pragma unroll
        for (int kk = 0; kk < BK; kk++) {
            float4 a0 = *(const float4*)&As[kk][ty * 8];
            float4 a1 = *(const float4*)&As[kk][ty * 8 + 4];
            float4 g4 = *(const float4*)&Bg[kk][tx * 4];
            float4 u4 = *(const float4*)&Bu[kk][tx * 4];
            float a[8] = {a0.x, a0.y, a0.z, a0.w, a1.x, a1.y, a1.z, a1.w};
            float bg[4] = {g4.x, g4.y, g4.z, g4.w};
            float bu[4] = {u4.x, u4.y, u4.z, u4.w};
#pragma unroll
            for (int i = 0; i < 8; i++) {
#pragma unroll
                for (int j = 0; j < 4; j++) {
                    accg[i][j] = fmaf(a[i], bg[j], accg[i][j]);
                    accu[i][j] = fmaf(a[i], bu[j], accu[i][j]);
                }
            }
        }
        __syncthreads();
    }
#pragma unroll
    for (int i = 0; i < 8; i++) {
        int row = m0 + ty * 8 + i;
        float4 hv;
        float g, u;
        g = accg[i][0]; u = accu[i][0]; hv.x = g / (1.f + expf(-g)) * u;
        g = accg[i][1]; u = accu[i][1]; hv.y = g / (1.f + expf(-g)) * u;
        g = accg[i][2]; u = accu[i][2]; hv.z = g / (1.f + expf(-g)) * u;
        g = accg[i][3]; u = accu[i][3]; hv.w = g / (1.f + expf(-g)) * u;
        *(float4*)(d_h + (size_t)(e * CAP + row) * HDIM + n0 + tx * 4) = hv;
    }
}

// ------- 6. GEMM2: ye = h @ W2^T --------------------------------------------
__global__ __launch_bounds__(256)
void gemm2_kernel(const float* __restrict__ W2)
{
    __shared__ float As[BK][132];
    __shared__ float Bs[BK][132];

    int e  = blockIdx.z;
    int m0 = blockIdx.y * 128;
    int n0 = blockIdx.x * 128;
    int t  = threadIdx.x;
    int tx = t & 15, ty = t >> 4;

    const float* Abase = d_h + (size_t)e * CAP * HDIM;
    const float* Bbase = W2 + (size_t)e * DDIM * HDIM;

    float acc[8][8];
#pragma unroll
    for (int i = 0; i < 8; i++)
#pragma unroll
        for (int j = 0; j < 8; j++) acc[i][j] = 0.f;

    for (int kt = 0; kt < HDIM / BK; kt++) {
        int k0 = kt * BK;
#pragma unroll
        for (int q = t; q < 512; q += 256) {
            int row = q >> 2, kq = (q & 3) << 2;
            float4 va = *(const float4*)(Abase + (size_t)(m0 + row) * HDIM + k0 + kq);
            As[kq + 0][row] = va.x; As[kq + 1][row] = va.y;
            As[kq + 2][row] = va.z; As[kq + 3][row] = va.w;
            float4 vb = *(const float4*)(Bbase + (size_t)(n0 + row) * HDIM + k0 + kq);
            Bs[kq + 0][row] = vb.x; Bs[kq + 1][row] = vb.y;
            Bs[kq + 2][row] = vb.z; Bs[kq + 3][row] = vb.w;
        }
        __syncthreads();
#pragma unroll
        for (int kk = 0; kk < BK; kk++) {
            float4 a0 = *(const float4*)&As[kk][ty * 8];
            float4 a1 = *(const float4*)&As[kk][ty * 8 + 4];
            float4 b0 = *(const float4*)&Bs[kk][tx * 8];
            float4 b1 = *(const float4*)&Bs[kk][tx * 8 + 4];
            float a[8] = {a0.x, a0.y, a0.z, a0.w, a1.x, a1.y, a1.z, a1.w};
            float b[8] = {b0.x, b0.y, b0.z, b0.w, b1.x, b1.y, b1.z, b1.w};
#pragma unroll
            for (int i = 0; i < 8; i++)
#pragma unroll
                for (int j = 0; j < 8; j++)
                    acc[i][j] = fmaf(a[i], b[j], acc[i][j]);
        }
        __syncthreads();
    }
#pragma unroll
    for (int i = 0; i < 8; i++) {
        int row = m0 + ty * 8 + i;
        float* dst = d_ye + (size_t)(e * CAP + row) * DDIM + n0 + tx * 8;
        *(float4*)(dst)     = make_float4(acc[i][0], acc[i][1], acc[i][2], acc[i][3]);
        *(float4*)(dst + 4) = make_float4(acc[i][4], acc[i][5], acc[i][6], acc[i][7]);
    }
}

// ------- 7. scatter back + top/keep outputs ---------------------------------
__global__ void scatter_kernel(float* __restrict__ out)
{
    int i = blockIdx.x;
    int t = threadIdx.x;                 // 256 threads, 256 float4 per row
    int kp = d_keep[i], e = d_top[i], s = d_slot[i];
    float4 v = make_float4(0.f, 0.f, 0.f, 0.f);
    if (kp) v = ((const float4*)(d_ye + (size_t)(e * CAP + s) * DDIM))[t];
    ((float4*)(out + (size_t)i * DDIM))[t] = v;
    if (t == 0) {
        out[OUT_TOP + i]  = (float)e;
        out[OUT_KEEP + i] = kp ? 1.f : 0.f;
    }
}

// ---------------- launch -----------------------------------------------------
extern "C" void kernel_launch(void* const* d_in, const int* in_sizes, int n_in,
                              void* d_out, int out_size)
{
    const float* x   = (const float*)d_in[0];
    const float* Wg  = (const float*)d_in[1];
    const float* W13 = (const float*)d_in[2];
    const float* W2  = (const float*)d_in[3];
    float* out = (float*)d_out;

    router_kernel<<<NTOK / 8, 256>>>(x, Wg);
    scan_kernel<<<1, 1024>>>();
    reduce_kernel<<<1, 1024>>>(out + OUT_AUX);
    gather_kernel<<<NE * CAP, 128>>>(x);

    dim3 g1(HDIM / 64, CAP / 128, NE);
    gemm1_kernel<<<g1, 256>>>(W13);

    dim3 g2(DDIM / 128, CAP / 128, NE);
    gemm2_kernel<<<g2, 256>>>(W2);

    scatter_kernel<<<NTOK, 256>>>(out);
}

// round 3
// speedup vs baseline: 4.1726x; 4.1726x over previous
#include <cuda_runtime.h>
#include <cstdint>
#include <math.h>

#define NTOK 8192
#define NE   8
#define DDIM 1024
#define HDIM 5632
#define H2   (2*HDIM)
#define CAP  1280

#define OUT_AUX  8388608
#define OUT_TOP  (8388608 + 1)
#define OUT_KEEP (8388608 + 1 + NTOK)

// ---------------- scratch ----------------
__device__ float d_probs[NTOK * NE];
__device__ float d_z2[NTOK];
__device__ int   d_top[NTOK];
__device__ int   d_keep[NTOK];
__device__ int   d_gidx[NE * CAP];
__device__ int   d_counts[NE];
__device__ int   d_counts_cap[NE];
__device__ __align__(256) float d_h[(size_t)NE * CAP * HDIM];   // 231 MB

// ---------------- helpers ----------------
__device__ __forceinline__ uint32_t tf32r(float x) {
    float y;
    asm("cvt.rna.tf32.f32 %0, %1;" : "=f"(y) : "f"(x));
    return __float_as_uint(y);
}
__device__ __forceinline__ void mma_tf32(float* c, const uint32_t* a,
                                         uint32_t b0, uint32_t b1) {
    asm volatile(
        "mma.sync.aligned.m16n8k8.row.col.f32.tf32.tf32.f32 "
        "{%0,%1,%2,%3}, {%4,%5,%6,%7}, {%8,%9}, {%0,%1,%2,%3};"
        : "+f"(c[0]), "+f"(c[1]), "+f"(c[2]), "+f"(c[3])
        : "r"(a[0]), "r"(a[1]), "r"(a[2]), "r"(a[3]), "r"(b0), "r"(b1));
}

#define LDP 36          // smem row stride (floats): banks = lane, STS.128-aligned

// ---------------- 1. router ----------------
__global__ void router_kernel(const float* __restrict__ x,
                              const float* __restrict__ Wg)
{
    __shared__ float sWg[NE * DDIM];
    int t = threadIdx.x;
    for (int i = t; i < NE * DDIM; i += 256) sWg[i] = Wg[i];
    __syncthreads();

    int warp = t >> 5, lane = t & 31;
    int tok  = blockIdx.x * 8 + warp;
    const float* xr = x + (size_t)tok * DDIM;

    float acc[NE];
#pragma unroll
    for (int e = 0; e < NE; e++) acc[e] = 0.f;
    for (int k = lane; k < DDIM; k += 32) {
        float xv = xr[k];
#pragma unroll
        for (int e = 0; e < NE; e++) acc[e] = fmaf(xv, sWg[e * DDIM + k], acc[e]);
    }
#pragma unroll
    for (int e = 0; e < NE; e++) {
#pragma unroll
        for (int o = 16; o > 0; o >>= 1)
            acc[e] += __shfl_down_sync(0xffffffffu, acc[e], o);
    }
    if (lane == 0) {
        float m = acc[0]; int am = 0;
#pragma unroll
        for (int e = 1; e < NE; e++) if (acc[e] > m) { m = acc[e]; am = e; }
        float p[NE]; float s = 0.f;
#pragma unroll
        for (int e = 0; e < NE; e++) { p[e] = expf(acc[e] - m); s += p[e]; }
        float inv = 1.f / s;
#pragma unroll
        for (int e = 0; e < NE; e++) d_probs[tok * NE + e] = p[e] * inv;
        float z = m + logf(s);
        d_z2[tok] = z * z;
        d_top[tok] = am;
    }
}

// ---------------- 2. ordered capacity scan ----------------
__global__ void scan_kernel()
{
    __shared__ unsigned long long s0[1024], s1[1024];
    __shared__ int base[NE];
    int t = threadIdx.x;
    if (t < NE) base[t] = 0;
    __syncthreads();

    for (int tile = 0; tile < NTOK / 1024; tile++) {
        int i = tile * 1024 + t;
        int e = d_top[i];
        unsigned long long v0 = (e < 4)  ? (1ULL << (16 * e))       : 0ULL;
        unsigned long long v1 = (e >= 4) ? (1ULL << (16 * (e - 4))) : 0ULL;
        s0[t] = v0; s1[t] = v1;
        __syncthreads();
        for (int off = 1; off < 1024; off <<= 1) {
            unsigned long long a0 = (t >= off) ? s0[t - off] : 0ULL;
            unsigned long long a1 = (t >= off) ? s1[t - off] : 0ULL;
            __syncthreads();
            s0[t] += a0; s1[t] += a1;
            __syncthreads();
        }
        unsigned long long w = (e < 4) ? s0[t] : s1[t];
        int sh   = 16 * (e & 3);
        int posl = (int)((w >> sh) & 0xFFFFULL) - 1;
        int pos  = base[e] + posl;
        int kp   = (pos < CAP) ? 1 : 0;
        d_keep[i] = kp;
        if (kp) d_gidx[e * CAP + pos] = i;
        __syncthreads();
        if (t < 4)      base[t] += (int)((s0[1023] >> (16 * t)) & 0xFFFFULL);
        else if (t < 8) base[t] += (int)((s1[1023] >> (16 * (t - 4))) & 0xFFFFULL);
        __syncthreads();
    }
    if (t < NE) {
        d_counts[t] = base[t];
        d_counts_cap[t] = base[t] < CAP ? base[t] : CAP;
    }
}

// ---------------- 3. aux loss ----------------
__global__ void reduce_kernel(float* __restrict__ out_aux)
{
    __shared__ float sm[1024];
    __shared__ float pe[NE];
    int t = threadIdx.x;
    float pp[NE];
#pragma unroll
    for (int e = 0; e < NE; e++) pp[e] = 0.f;
    float zz = 0.f;
    for (int i = t; i < NTOK; i += 1024) {
#pragma unroll
        for (int e = 0; e < NE; e++) pp[e] += d_probs[i * NE + e];
        zz += d_z2[i];
    }
#pragma unroll
    for (int e = 0; e < NE; e++) {
        sm[t] = pp[e]; __syncthreads();
        for (int o = 512; o > 0; o >>= 1) {
            if (t < o) sm[t] += sm[t + o];
            __syncthreads();
        }
        if (t == 0) pe[e] = sm[0];
        __syncthreads();
    }
    sm[t] = zz; __syncthreads();
    for (int o = 512; o > 0; o >>= 1) {
        if (t < o) sm[t] += sm[t + o];
        __syncthreads();
    }
    if (t == 0) {
        float bal = 0.f;
        for (int e = 0; e < NE; e++)
            bal += (pe[e] / (float)NTOK) * ((float)d_counts[e] / (float)NTOK);
        bal *= 0.01f * (float)NE;
        out_aux[0] = bal + (sm[0] / (float)NTOK) * 0.001f;
    }
}

// ---------------- 4. GEMM1: h = silu(xe@Wg^T)*(xe@Wu^T), tf32 mma.sync ------
// block tile 128 rows x 64 h-cols (g and u both), warp tile 32x32, 8 warps
#define SMEM1 (4 * 128 * LDP * 4)   // A[2] + B[2], B rows: 64 g + 64 u

__global__ __launch_bounds__(256, 1)
void gemm1_kernel(const float* __restrict__ x, const float* __restrict__ W13)
{
    extern __shared__ float sm[];
    float* As = sm;                    // [2][128][LDP]
    float* Bs = sm + 2 * 128 * LDP;    // [2][128][LDP]
    __shared__ int s_tok[128];

    const int t = threadIdx.x, wid = t >> 5, lane = t & 31;
    const int lr = lane >> 2, lc = lane & 3;
    const int warpM = wid & 3, warpN = wid >> 2;
    const int e = blockIdx.z, m0 = blockIdx.x * 128, nb = blockIdx.y;

    if (t < 128) {
        int cc = d_counts_cap[e];
        s_tok[t] = (m0 + t < cc) ? d_gidx[e * CAP + m0 + t] : 0;
    }
    __syncthreads();

    // loader mapping: idx = t + i*256, row = idx>>3, q = idx&7
    const float* aptr[4];
    const float* bptr[4];
#pragma unroll
    for (int i = 0; i < 4; i++) {
        int idx = t + i * 256, row = idx >> 3, q = idx & 7;
        aptr[i] = x + (size_t)s_tok[row] * DDIM + q * 4;
        int wr = (row < 64) ? (nb * 64 + row) : (HDIM + nb * 64 + row - 64);
        bptr[i] = W13 + ((size_t)e * H2 + wr) * DDIM + q * 4;
    }
    const int sts_off0 = ((t + 0)   >> 3) * LDP + ((t + 0)   & 7) * 4;
    // per-i STS offsets
    float cg[2][4][4], cu[2][4][4];
#pragma unroll
    for (int a = 0; a < 2; a++)
#pragma unroll
        for (int b = 0; b < 4; b++)
#pragma unroll
            for (int r = 0; r < 4; r++) { cg[a][b][r] = 0.f; cu[a][b][r] = 0.f; }

    float4 ra[4], rb[4];
#pragma unroll
    for (int i = 0; i < 4; i++) { ra[i] = *(const float4*)(aptr[i]); rb[i] = *(const float4*)(bptr[i]); }

    const int KT = DDIM / 32;
    for (int kt = 0; kt < KT; kt++) {
        const int buf = kt & 1;
        float* Ab = As + buf * 128 * LDP;
        float* Bb = Bs + buf * 128 * LDP;
#pragma unroll
        for (int i = 0; i < 4; i++) {
            int idx = t + i * 256, row = idx >> 3, q = idx & 7;
            int so = row * LDP + q * 4;
            uint32_t* d = (uint32_t*)(Ab + so);
            d[0] = tf32r(ra[i].x); d[1] = tf32r(ra[i].y);
            d[2] = tf32r(ra[i].z); d[3] = tf32r(ra[i].w);
            uint32_t* d2 = (uint32_t*)(Bb + so);
            d2[0] = tf32r(rb[i].x); d2[1] = tf32r(rb[i].y);
            d2[2] = tf32r(rb[i].z); d2[3] = tf32r(rb[i].w);
        }
        __syncthreads();
        if (kt + 1 < KT) {
            int k0 = (kt + 1) * 32;
#pragma unroll
            for (int i = 0; i < 4; i++) {
                ra[i] = *(const float4*)(aptr[i] + k0);
                rb[i] = *(const float4*)(bptr[i] + k0);
            }
        }
#pragma unroll
        for (int kk = 0; kk < 4; kk++) {
            const int kb = kk * 8;
            uint32_t af[2][4];
#pragma unroll
            for (int mf = 0; mf < 2; mf++) {
                int rbse = warpM * 32 + mf * 16;
                const uint32_t* A32 = (const uint32_t*)Ab;
                af[mf][0] = A32[(rbse + lr) * LDP + kb + lc];
                af[mf][1] = A32[(rbse + 8 + lr) * LDP + kb + lc];
                af[mf][2] = A32[(rbse + lr) * LDP + kb + 4 + lc];
                af[mf][3] = A32[(rbse + 8 + lr) * LDP + kb + 4 + lc];
            }
            const uint32_t* B32 = (const uint32_t*)Bb;
#pragma unroll
            for (int nf = 0; nf < 4; nf++) {
                int nbse = warpN * 32 + nf * 8;
                uint32_t bg0 = B32[(nbse + lr) * LDP + kb + lc];
                uint32_t bg1 = B32[(nbse + lr) * LDP + kb + 4 + lc];
                uint32_t bu0 = B32[(64 + nbse + lr) * LDP + kb + lc];
                uint32_t bu1 = B32[(64 + nbse + lr) * LDP + kb + 4 + lc];
#pragma unroll
                for (int mf = 0; mf < 2; mf++) {
                    mma_tf32(cg[mf][nf], af[mf], bg0, bg1);
                    mma_tf32(cu[mf][nf], af[mf], bu0, bu1);
                }
            }
        }
        __syncthreads();
    }

    // epilogue: h = silu(g)*u, write float2 pairs
#pragma unroll
    for (int mf = 0; mf < 2; mf++) {
        int r0 = m0 + warpM * 32 + mf * 16 + lr;
#pragma unroll
        for (int nf = 0; nf < 4; nf++) {
            int col = nb * 64 + warpN * 32 + nf * 8 + 2 * lc;
            float g0 = cg[mf][nf][0], g1 = cg[mf][nf][1];
            float u0 = cu[mf][nf][0], u1 = cu[mf][nf][1];
            float2 h0 = make_float2(g0 * u0 / (1.f + expf(-g0)),
                                    g1 * u1 / (1.f + expf(-g1)));
            *(float2*)(d_h + ((size_t)e * CAP + r0) * HDIM + col) = h0;
            float g2 = cg[mf][nf][2], g3 = cg[mf][nf][3];
            float u2 = cu[mf][nf][2], u3 = cu[mf][nf][3];
            float2 h1 = make_float2(g2 * u2 / (1.f + expf(-g2)),
                                    g3 * u3 / (1.f + expf(-g3)));
            *(float2*)(d_h + ((size_t)e * CAP + r0 + 8) * HDIM + col) = h1;
        }
    }
    (void)sts_off0;
}

// ---------------- 5. GEMM2: y = h @ W2^T, scatter to out -------------------
// block tile 128 x 128, warp tile 32x64, 8 warps
#define SMEM2 (4 * 128 * LDP * 4)

__global__ __launch_bounds__(256, 1)
void gemm2_kernel(const float* __restrict__ W2, float* __restrict__ out)
{
    extern __shared__ float sm[];
    float* As = sm;
    float* Bs = sm + 2 * 128 * LDP;
    __shared__ int s_tok[128];

    const int t = threadIdx.x, wid = t >> 5, lane = t & 31;
    const int lr = lane >> 2, lc = lane & 3;
    const int warpM = wid & 3, warpN = wid >> 2;
    const int e = blockIdx.z, m0 = blockIdx.x * 128, nb = blockIdx.y;

    if (t < 128) {
        int cc = d_counts_cap[e];
        s_tok[t] = (m0 + t < cc) ? d_gidx[e * CAP + m0 + t] : -1;
    }
    __syncthreads();

    const float* aptr[4];
    const float* bptr[4];
#pragma unroll
    for (int i = 0; i < 4; i++) {
        int idx = t + i * 256, row = idx >> 3, q = idx & 7;
        aptr[i] = d_h + ((size_t)e * CAP + m0 + row) * HDIM + q * 4;
        bptr[i] = W2 + ((size_t)e * DDIM + nb * 128 + row) * HDIM + q * 4;
    }

    float c[2][8][4];
#pragma unroll
    for (int a = 0; a < 2; a++)
#pragma unroll
        for (int b = 0; b < 8; b++)
#pragma unroll
            for (int r = 0; r < 4; r++) c[a][b][r] = 0.f;

    float4 ra[4], rb[4];
#pragma unroll
    for (int i = 0; i < 4; i++) { ra[i] = *(const float4*)(aptr[i]); rb[i] = *(const float4*)(bptr[i]); }

    const int KT = HDIM / 32;
    for (int kt = 0; kt < KT; kt++) {
        const int buf = kt & 1;
        float* Ab = As + buf * 128 * LDP;
        float* Bb = Bs + buf * 128 * LDP;
#pragma unroll
        for (int i = 0; i < 4; i++) {
            int idx = t + i * 256, row = idx >> 3, q = idx & 7;
            int so = row * LDP + q * 4;
            uint32_t* d = (uint32_t*)(Ab + so);
            d[0] = tf32r(ra[i].x); d[1] = tf32r(ra[i].y);
            d[2] = tf32r(ra[i].z); d[3] = tf32r(ra[i].w);
            uint32_t* d2 = (uint32_t*)(Bb + so);
            d2[0] = tf32r(rb[i].x); d2[1] = tf32r(rb[i].y);
            d2[2] = tf32r(rb[i].z); d2[3] = tf32r(rb[i].w);
        }
        __syncthreads();
        if (kt + 1 < KT) {
            int k0 = (kt + 1) * 32;
#pragma unroll
            for (int i = 0; i < 4; i++) {
                ra[i] = *(const float4*)(aptr[i] + k0);
                rb[i] = *(const float4*)(bptr[i] + k0);
            }
        }
#pragma unroll
        for (int kk = 0; kk < 4; kk++) {
            const int kb = kk * 8;
            uint32_t af[2][4];
            const uint32_t* A32 = (const uint32_t*)Ab;
#pragma unroll
            for (int mf = 0; mf < 2; mf++) {
                int rbse = warpM * 32 + mf * 16;
                af[mf][0] = A32[(rbse + lr) * LDP + kb + lc];
                af[mf][1] = A32[(rbse + 8 + lr) * LDP + kb + lc];
                af[mf][2] = A32[(rbse + lr) * LDP + kb + 4 + lc];
                af[mf][3] = A32[(rbse + 8 + lr) * LDP + kb + 4 + lc];
            }
            const uint32_t* B32 = (const uint32_t*)Bb;
#pragma unroll
            for (int nf = 0; nf < 8; nf++) {
                int nbse = warpN * 64 + nf * 8;
                uint32_t b0 = B32[(nbse + lr) * LDP + kb + lc];
                uint32_t b1 = B32[(nbse + lr) * LDP + kb + 4 + lc];
#pragma unroll
                for (int mf = 0; mf < 2; mf++)
                    mma_tf32(c[mf][nf], af[mf], b0, b1);
            }
        }
        __syncthreads();
    }

    // epilogue: scatter rows to out[token]
#pragma unroll
    for (int mf = 0; mf < 2; mf++) {
        int rl0 = warpM * 32 + mf * 16 + lr;
        int tok0 = s_tok[rl0];
        int tok1 = s_tok[rl0 + 8];
#pragma unroll
        for (int nf = 0; nf < 8; nf++) {
            int col = nb * 128 + warpN * 64 + nf * 8 + 2 * lc;
            if (tok0 >= 0)
                *(float2*)(out + (size_t)tok0 * DDIM + col) =
                    make_float2(c[mf][nf][0], c[mf][nf][1]);
            if (tok1 >= 0)
                *(float2*)(out + (size_t)tok1 * DDIM + col) =
                    make_float2(c[mf][nf][2], c[mf][nf][3]);
        }
    }
}

// ---------------- 6. finalize ----------------
__global__ void finalize_kernel(float* __restrict__ out)
{
    int i = blockIdx.x, t = threadIdx.x;
    int kp = d_keep[i];
    if (!kp)
        ((float4*)(out + (size_t)i * DDIM))[t] = make_float4(0.f, 0.f, 0.f, 0.f);
    if (t == 0) {
        out[OUT_TOP + i]  = (float)d_top[i];
        out[OUT_KEEP + i] = kp ? 1.f : 0.f;
    }
}

// ---------------- launch ----------------
extern "C" void kernel_launch(void* const* d_in, const int* in_sizes, int n_in,
                              void* d_out, int out_size)
{
    const float* x   = (const float*)d_in[0];
    const float* Wg  = (const float*)d_in[1];
    const float* W13 = (const float*)d_in[2];
    const float* W2  = (const float*)d_in[3];
    float* out = (float*)d_out;

    cudaFuncSetAttribute(gemm1_kernel, cudaFuncAttributeMaxDynamicSharedMemorySize, SMEM1);
    cudaFuncSetAttribute(gemm2_kernel, cudaFuncAttributeMaxDynamicSharedMemorySize, SMEM2);

    router_kernel<<<NTOK / 8, 256>>>(x, Wg);
    scan_kernel<<<1, 1024>>>();
    reduce_kernel<<<1, 1024>>>(out + OUT_AUX);

    dim3 g1(CAP / 128, HDIM / 64, NE);     // 10 x 88 x 8 (m fastest: B-tile L2 reuse)
    gemm1_kernel<<<g1, 256, SMEM1>>>(x, W13);

    dim3 g2(CAP / 128, DDIM / 128, NE);    // 10 x 8 x 8
    gemm2_kernel<<<g2, 256, SMEM2>>>(W2, out);

    finalize_kernel<<<NTOK, 256>>>(out);
}

// round 4
// speedup vs baseline: 4.2148x; 1.0101x over previous
#include <cuda_runtime.h>
#include <cstdint>
#include <math.h>

#define NTOK 8192
#define NE   8
#define DDIM 1024
#define HDIM 5632
#define H2   (2*HDIM)
#define CAP  1280

#define OUT_AUX  8388608
#define OUT_TOP  (8388608 + 1)
#define OUT_KEEP (8388608 + 1 + NTOK)

// ---------------- scratch ----------------
__device__ float d_probs[NTOK * NE];
__device__ float d_z2[NTOK];
__device__ int   d_top[NTOK];
__device__ int   d_keep[NTOK];
__device__ int   d_gidx[NE * CAP];
__device__ int   d_counts[NE];
__device__ int   d_counts_cap[NE];
__device__ __align__(256) float d_h[(size_t)NE * CAP * HDIM];        // 231 MB
__device__ __align__(256) float d_xr[(size_t)NTOK * DDIM];           //  33 MB
__device__ __align__(256) float d_w13r[(size_t)NE * H2 * DDIM];      // 369 MB
__device__ __align__(256) float d_w2r[(size_t)NE * DDIM * HDIM];     // 184 MB

// ---------------- helpers ----------------
__device__ __forceinline__ uint32_t tf32r(float x) {
    float y;
    asm("cvt.rna.tf32.f32 %0, %1;" : "=f"(y) : "f"(x));
    return __float_as_uint(y);
}
__device__ __forceinline__ void mma_tf32(float* c, const uint32_t* a,
                                         uint32_t b0, uint32_t b1) {
    asm volatile(
        "mma.sync.aligned.m16n8k8.row.col.f32.tf32.tf32.f32 "
        "{%0,%1,%2,%3}, {%4,%5,%6,%7}, {%8,%9}, {%0,%1,%2,%3};"
        : "+f"(c[0]), "+f"(c[1]), "+f"(c[2]), "+f"(c[3])
        : "r"(a[0]), "r"(a[1]), "r"(a[2]), "r"(a[3]), "r"(b0), "r"(b1));
}
__device__ __forceinline__ uint32_t smem_u32(const void* p) {
    uint32_t a;
    asm("{ .reg .u64 t; cvta.to.shared.u64 t, %1; cvt.u32.u64 %0, t; }"
        : "=r"(a) : "l"(p));
    return a;
}
#define CP16(d, s) \
    asm volatile("cp.async.cg.shared.global [%0], [%1], 16;" :: "r"(d), "l"(s))
#define CPCOMMIT() asm volatile("cp.async.commit_group;")
#define CPWAIT1()  asm volatile("cp.async.wait_group 1;")

// ---------------- 0. tf32 pre-round ----------------
__global__ void round_kernel(const float4* __restrict__ src,
                             float4* __restrict__ dst, int n4)
{
    int i = blockIdx.x * blockDim.x + threadIdx.x;
    if (i < n4) {
        float4 v = src[i];
        v.x = __uint_as_float(tf32r(v.x));
        v.y = __uint_as_float(tf32r(v.y));
        v.z = __uint_as_float(tf32r(v.z));
        v.w = __uint_as_float(tf32r(v.w));
        dst[i] = v;
    }
}

// ---------------- 1. router ----------------
__global__ void router_kernel(const float* __restrict__ x,
                              const float* __restrict__ Wg)
{
    __shared__ float sWg[NE * DDIM];
    int t = threadIdx.x;
    for (int i = t; i < NE * DDIM; i += 256) sWg[i] = Wg[i];
    __syncthreads();

    int warp = t >> 5, lane = t & 31;
    int tok  = blockIdx.x * 8 + warp;
    const float* xr = x + (size_t)tok * DDIM;

    float acc[NE];
#pragma unroll
    for (int e = 0; e < NE; e++) acc[e] = 0.f;
    for (int k = lane; k < DDIM; k += 32) {
        float xv = xr[k];
#pragma unroll
        for (int e = 0; e < NE; e++) acc[e] = fmaf(xv, sWg[e * DDIM + k], acc[e]);
    }
#pragma unroll
    for (int e = 0; e < NE; e++) {
#pragma unroll
        for (int o = 16; o > 0; o >>= 1)
            acc[e] += __shfl_down_sync(0xffffffffu, acc[e], o);
    }
    if (lane == 0) {
        float m = acc[0]; int am = 0;
#pragma unroll
        for (int e = 1; e < NE; e++) if (acc[e] > m) { m = acc[e]; am = e; }
        float p[NE]; float s = 0.f;
#pragma unroll
        for (int e = 0; e < NE; e++) { p[e] = expf(acc[e] - m); s += p[e]; }
        float inv = 1.f / s;
#pragma unroll
        for (int e = 0; e < NE; e++) d_probs[tok * NE + e] = p[e] * inv;
        float z = m + logf(s);
        d_z2[tok] = z * z;
        d_top[tok] = am;
    }
}

// ---------------- 2. ordered capacity scan ----------------
__global__ void scan_kernel()
{
    __shared__ unsigned long long s0[1024], s1[1024];
    __shared__ int base[NE];
    int t = threadIdx.x;
    if (t < NE) base[t] = 0;
    __syncthreads();

    for (int tile = 0; tile < NTOK / 1024; tile++) {
        int i = tile * 1024 + t;
        int e = d_top[i];
        unsigned long long v0 = (e < 4)  ? (1ULL << (16 * e))       : 0ULL;
        unsigned long long v1 = (e >= 4) ? (1ULL << (16 * (e - 4))) : 0ULL;
        s0[t] = v0; s1[t] = v1;
        __syncthreads();
        for (int off = 1; off < 1024; off <<= 1) {
            unsigned long long a0 = (t >= off) ? s0[t - off] : 0ULL;
            unsigned long long a1 = (t >= off) ? s1[t - off] : 0ULL;
            __syncthreads();
            s0[t] += a0; s1[t] += a1;
            __syncthreads();
        }
        unsigned long long w = (e < 4) ? s0[t] : s1[t];
        int sh   = 16 * (e & 3);
        int posl = (int)((w >> sh) & 0xFFFFULL) - 1;
        int pos  = base[e] + posl;
        int kp   = (pos < CAP) ? 1 : 0;
        d_keep[i] = kp;
        if (kp) d_gidx[e * CAP + pos] = i;
        __syncthreads();
        if (t < 4)      base[t] += (int)((s0[1023] >> (16 * t)) & 0xFFFFULL);
        else if (t < 8) base[t] += (int)((s1[1023] >> (16 * (t - 4))) & 0xFFFFULL);
        __syncthreads();
    }
    if (t < NE) {
        d_counts[t] = base[t];
        d_counts_cap[t] = base[t] < CAP ? base[t] : CAP;
    }
}

// ---------------- 3. aux loss ----------------
__global__ void reduce_kernel(float* __restrict__ out_aux)
{
    __shared__ float sm[1024];
    __shared__ float pe[NE];
    int t = threadIdx.x;
    float pp[NE];
#pragma unroll
    for (int e = 0; e < NE; e++) pp[e] = 0.f;
    float zz = 0.f;
    for (int i = t; i < NTOK; i += 1024) {
#pragma unroll
        for (int e = 0; e < NE; e++) pp[e] += d_probs[i * NE + e];
        zz += d_z2[i];
    }
#pragma unroll
    for (int e = 0; e < NE; e++) {
        sm[t] = pp[e]; __syncthreads();
        for (int o = 512; o > 0; o >>= 1) {
            if (t < o) sm[t] += sm[t + o];
            __syncthreads();
        }
        if (t == 0) pe[e] = sm[0];
        __syncthreads();
    }
    sm[t] = zz; __syncthreads();
    for (int o = 512; o > 0; o >>= 1) {
        if (t < o) sm[t] += sm[t + o];
        __syncthreads();
    }
    if (t == 0) {
        float bal = 0.f;
        for (int e = 0; e < NE; e++)
            bal += (pe[e] / (float)NTOK) * ((float)d_counts[e] / (float)NTOK);
        bal *= 0.01f * (float)NE;
        out_aux[0] = bal + (sm[0] / (float)NTOK) * 0.001f;
    }
}

// ---------------- 4/5. tf32 mma.sync GEMMs, cp.async 3-stage --------------
// SW128 swizzle, 128x32-float tiles (128B rows), 2 CTAs/SM.
// MODE 0: h = silu(xe@Wg^T)*(xe@Wu^T)  (A = gathered x, K=1024, N-tile 64g+64u)
// MODE 1: out = h@W2^T scattered        (A = d_h,       K=5632, N-tile 128)
#define STG_F  8192                // floats per stage (A 4096 + B 4096)
#define SMEM_G (3 * STG_F * 4)     // 98304 B

template<int MODE>
__global__ __launch_bounds__(256, 2)
void moe_gemm(float* __restrict__ out)
{
    constexpr int KT = (MODE == 0) ? DDIM / 32 : HDIM / 32;

    extern __shared__ float sm[];
    __shared__ int s_tok[128];

    const int t = threadIdx.x, wid = t >> 5, lane = t & 31;
    const int lr = lane >> 2, lc = lane & 3;
    const int warpM = wid & 3, warpN = wid >> 2;
    const int e = blockIdx.z, m0 = blockIdx.x * 128, nb = blockIdx.y;

    if (t < 128) {
        int cc = d_counts_cap[e];
        s_tok[t] = (m0 + t < cc) ? d_gidx[e * CAP + m0 + t] : ((MODE == 0) ? 0 : -1);
    }
    __syncthreads();

    const uint32_t sbase = smem_u32(sm);
    const int row = t >> 1;                // loader: 2 threads/row, q = 4*(t&1)..
    const int q0l = (t & 1) * 4;

    // issue one stage: A rows 128 x 8 chunks + B rows 128 x 8 chunks
    auto load_stage = [&](int kt, int s) {
        const uint32_t ab = sbase + (uint32_t)s * (STG_F * 4);
        const uint32_t bb = ab + 4096 * 4;
        const int k0 = kt * 32;
#pragma unroll
        for (int c = 0; c < 4; c++) {
            int q = q0l + c;
            uint32_t dsw = (uint32_t)((q ^ (row & 7)) * 16 + row * 128);
            const float* srcA;
            if (MODE == 0)
                srcA = d_xr + (size_t)s_tok[row] * DDIM + k0 + q * 4;
            else
                srcA = d_h + ((size_t)e * CAP + m0 + row) * HDIM + k0 + q * 4;
            CP16(ab + dsw, srcA);
            const float* srcB;
            if (MODE == 0) {
                int wr = (row < 64) ? (nb * 64 + row) : (HDIM + nb * 64 + row - 64);
                srcB = d_w13r + ((size_t)e * H2 + wr) * DDIM + k0 + q * 4;
            } else {
                srcB = d_w2r + ((size_t)e * DDIM + nb * 128 + row) * HDIM + k0 + q * 4;
            }
            CP16(bb + dsw, srcB);
        }
    };

    float c0[2][4][4], c1[2][4][4];   // MODE0: g,u ; MODE1: n-lo, n-hi
#pragma unroll
    for (int a = 0; a < 2; a++)
#pragma unroll
        for (int b = 0; b < 4; b++)
#pragma unroll
            for (int r = 0; r < 4; r++) { c0[a][b][r] = 0.f; c1[a][b][r] = 0.f; }

    load_stage(0, 0); CPCOMMIT();
    load_stage(1, 1); CPCOMMIT();

    for (int kt = 0; kt < KT; kt++) {
        CPWAIT1();
        __syncthreads();
        if (kt + 2 < KT) load_stage(kt + 2, (kt + 2) % 3);
        CPCOMMIT();

        const uint32_t* A32 = (const uint32_t*)(sm + (size_t)(kt % 3) * STG_F);
        const uint32_t* B32 = A32 + 4096;
#pragma unroll
        for (int kk = 0; kk < 4; kk++) {
            const int cq0 = ((kk * 2) ^ lr) * 4 + lc;
            const int cq1 = ((kk * 2 + 1) ^ lr) * 4 + lc;
            uint32_t af[2][4];
#pragma unroll
            for (int mf = 0; mf < 2; mf++) {
                int rb = warpM * 32 + mf * 16 + lr;
                af[mf][0] = A32[rb * 32 + cq0];
                af[mf][1] = A32[(rb + 8) * 32 + cq0];
                af[mf][2] = A32[rb * 32 + cq1];
                af[mf][3] = A32[(rb + 8) * 32 + cq1];
            }
#pragma unroll
            for (int nf = 0; nf < 4; nf++) {
                int nr0, nr1;
                if (MODE == 0) {            // g rows 0..63, u rows 64..127
                    nr0 = warpN * 32 + nf * 8 + lr;
                    nr1 = nr0 + 64;
                } else {                    // 64-wide n tile split
                    nr0 = warpN * 64 + nf * 8 + lr;
                    nr1 = nr0 + 32;
                }
                uint32_t b00 = B32[nr0 * 32 + cq0];
                uint32_t b01 = B32[nr0 * 32 + cq1];
                uint32_t b10 = B32[nr1 * 32 + cq0];
                uint32_t b11 = B32[nr1 * 32 + cq1];
#pragma unroll
                for (int mf = 0; mf < 2; mf++) {
                    mma_tf32(c0[mf][nf], af[mf], b00, b01);
                    mma_tf32(c1[mf][nf], af[mf], b10, b11);
                }
            }
        }
        __syncthreads();
    }

    if (MODE == 0) {
        // h = silu(g)*u, store tf32-rounded (same values GEMM2 would cvt)
#pragma unroll
        for (int mf = 0; mf < 2; mf++) {
            int r0 = m0 + warpM * 32 + mf * 16 + lr;
#pragma unroll
            for (int nf = 0; nf < 4; nf++) {
                int col = nb * 64 + warpN * 32 + nf * 8 + 2 * lc;
#pragma unroll
                for (int hh = 0; hh < 2; hh++) {
                    float g0 = c0[mf][nf][2 * hh], g1 = c0[mf][nf][2 * hh + 1];
                    float u0 = c1[mf][nf][2 * hh], u1 = c1[mf][nf][2 * hh + 1];
                    float h0 = g0 * u0 / (1.f + expf(-g0));
                    float h1 = g1 * u1 / (1.f + expf(-g1));
                    float2 hv = make_float2(__uint_as_float(tf32r(h0)),
                                            __uint_as_float(tf32r(h1)));
                    *(float2*)(d_h + ((size_t)e * CAP + r0 + 8 * hh) * HDIM + col) = hv;
                }
            }
        }
    } else {
        // scatter to out[token]
#pragma unroll
        for (int mf = 0; mf < 2; mf++) {
            int rl = warpM * 32 + mf * 16 + lr;
            int tok0 = s_tok[rl], tok1 = s_tok[rl + 8];
#pragma unroll
            for (int nf = 0; nf < 4; nf++) {
                int colA = nb * 128 + warpN * 64 + nf * 8 + 2 * lc;
                int colB = colA + 32;
                if (tok0 >= 0) {
                    *(float2*)(out + (size_t)tok0 * DDIM + colA) =
                        make_float2(c0[mf][nf][0], c0[mf][nf][1]);
                    *(float2*)(out + (size_t)tok0 * DDIM + colB) =
                        make_float2(c1[mf][nf][0], c1[mf][nf][1]);
                }
                if (tok1 >= 0) {
                    *(float2*)(out + (size_t)tok1 * DDIM + colA) =
                        make_float2(c0[mf][nf][2], c0[mf][nf][3]);
                    *(float2*)(out + (size_t)tok1 * DDIM + colB) =
                        make_float2(c1[mf][nf][2], c1[mf][nf][3]);
                }
            }
        }
    }
}

// ---------------- 6. finalize ----------------
__global__ void finalize_kernel(float* __restrict__ out)
{
    int i = blockIdx.x, t = threadIdx.x;
    int kp = d_keep[i];
    if (!kp)
        ((float4*)(out + (size_t)i * DDIM))[t] = make_float4(0.f, 0.f, 0.f, 0.f);
    if (t == 0) {
        out[OUT_TOP + i]  = (float)d_top[i];
        out[OUT_KEEP + i] = kp ? 1.f : 0.f;
    }
}

// ---------------- launch ----------------
extern "C" void kernel_launch(void* const* d_in, const int* in_sizes, int n_in,
                              void* d_out, int out_size)
{
    const float* x   = (const float*)d_in[0];
    const float* Wg  = (const float*)d_in[1];
    const float* W13 = (const float*)d_in[2];
    const float* W2  = (const float*)d_in[3];
    float* out = (float*)d_out;

    cudaFuncSetAttribute(moe_gemm<0>, cudaFuncAttributeMaxDynamicSharedMemorySize, SMEM_G);
    cudaFuncSetAttribute(moe_gemm<1>, cudaFuncAttributeMaxDynamicSharedMemorySize, SMEM_G);

    float* xr;  cudaGetSymbolAddress((void**)&xr,  d_xr);
    float* w13r; cudaGetSymbolAddress((void**)&w13r, d_w13r);
    float* w2r; cudaGetSymbolAddress((void**)&w2r, d_w2r);

    const int n4x  = NTOK * DDIM / 4;
    const int n4w1 = NE * H2 * DDIM / 4;
    const int n4w2 = NE * DDIM * HDIM / 4;
    round_kernel<<<(n4x  + 255) / 256, 256>>>((const float4*)x,   (float4*)xr,  n4x);
    round_kernel<<<(n4w1 + 255) / 256, 256>>>((const float4*)W13, (float4*)w13r, n4w1);
    round_kernel<<<(n4w2 + 255) / 256, 256>>>((const float4*)W2,  (float4*)w2r,  n4w2);

    router_kernel<<<NTOK / 8, 256>>>(x, Wg);
    scan_kernel<<<1, 1024>>>();
    reduce_kernel<<<1, 1024>>>(out + OUT_AUX);

    dim3 g1(CAP / 128, HDIM / 64, NE);     // 10 x 88 x 8
    moe_gemm<0><<<g1, 256, SMEM_G>>>(nullptr);

    dim3 g2(CAP / 128, DDIM / 128, NE);    // 10 x 8 x 8
    moe_gemm<1><<<g2, 256, SMEM_G>>>(out);

    finalize_kernel<<<NTOK, 256>>>(out);
}

// round 6
// speedup vs baseline: 7.1810x; 1.7038x over previous
#include <cuda_runtime.h>
#include <cuda_fp16.h>
#include <cstdint>
#include <math.h>

#define NTOK 8192
#define NE   8
#define DDIM 1024
#define HDIM 5632
#define H2   (2*HDIM)
#define CAP  1280

#define OUT_AUX  8388608
#define OUT_TOP  (8388608 + 1)
#define OUT_KEEP (8388608 + 1 + NTOK)

// ---------------- scratch ----------------
__device__ float d_probs[NTOK * NE];
__device__ float d_z2[NTOK];
__device__ int   d_top[NTOK];
__device__ int   d_keep[NTOK];
__device__ int   d_gidx[NE * CAP];
__device__ int   d_counts[NE];
__device__ int   d_counts_cap[NE];
__device__ __align__(256) __half d_hh[(size_t)NE * CAP * HDIM];     // 115 MB
__device__ __align__(256) __half d_xh[(size_t)NTOK * DDIM];         //  17 MB
__device__ __align__(256) __half d_w13h[(size_t)NE * H2 * DDIM];    // 184 MB
__device__ __align__(256) __half d_w2h[(size_t)NE * DDIM * HDIM];   //  92 MB

// ---------------- helpers ----------------
__device__ __forceinline__ uint32_t smem_u32(const void* p) {
    uint32_t a;
    asm("{ .reg .u64 t; cvta.to.shared.u64 t, %1; cvt.u32.u64 %0, t; }"
        : "=r"(a) : "l"(p));
    return a;
}
__device__ __forceinline__ uint32_t h2_u32(__half2 h) {
    return *reinterpret_cast<uint32_t*>(&h);
}
__device__ __forceinline__ void mma_f16(float* c, const uint32_t* a,
                                        uint32_t b0, uint32_t b1) {
    asm volatile(
        "mma.sync.aligned.m16n8k16.row.col.f32.f16.f16.f32 "
        "{%0,%1,%2,%3}, {%4,%5,%6,%7}, {%8,%9}, {%0,%1,%2,%3};"
        : "+f"(c[0]), "+f"(c[1]), "+f"(c[2]), "+f"(c[3])
        : "r"(a[0]), "r"(a[1]), "r"(a[2]), "r"(a[3]), "r"(b0), "r"(b1));
}
#define LDSM4(r0, r1, r2, r3, a) \
    asm volatile("ldmatrix.sync.aligned.m8n8.x4.shared.b16 {%0,%1,%2,%3}, [%4];" \
                 : "=r"(r0), "=r"(r1), "=r"(r2), "=r"(r3) : "r"(a))
#define CP16(d, s) \
    asm volatile("cp.async.cg.shared.global [%0], [%1], 16;" :: "r"(d), "l"(s))
#define CPCOMMIT() asm volatile("cp.async.commit_group;")
#define CPWAIT1()  asm volatile("cp.async.wait_group 1;")

// ---------------- 0. fp32 -> fp16 conversion ----------------
__global__ void cvt_kernel(const float4* __restrict__ src,
                           uint2* __restrict__ dst, int n4)
{
    int i = blockIdx.x * blockDim.x + threadIdx.x;
    if (i < n4) {
        float4 v = src[i];
        __half2 lo = __floats2half2_rn(v.x, v.y);
        __half2 hi = __floats2half2_rn(v.z, v.w);
        dst[i] = make_uint2(h2_u32(lo), h2_u32(hi));
    }
}

// ---------------- 1. router ----------------
__global__ void router_kernel(const float* __restrict__ x,
                              const float* __restrict__ Wg)
{
    __shared__ float sWg[NE * DDIM];
    int t = threadIdx.x;
    for (int i = t; i < NE * DDIM; i += 256) sWg[i] = Wg[i];
    __syncthreads();

    int warp = t >> 5, lane = t & 31;
    int tok  = blockIdx.x * 8 + warp;
    const float* xr = x + (size_t)tok * DDIM;

    float acc[NE];
#pragma unroll
    for (int e = 0; e < NE; e++) acc[e] = 0.f;
    for (int k = lane; k < DDIM; k += 32) {
        float xv = xr[k];
#pragma unroll
        for (int e = 0; e < NE; e++) acc[e] = fmaf(xv, sWg[e * DDIM + k], acc[e]);
    }
#pragma unroll
    for (int e = 0; e < NE; e++) {
#pragma unroll
        for (int o = 16; o > 0; o >>= 1)
            acc[e] += __shfl_down_sync(0xffffffffu, acc[e], o);
    }
    if (lane == 0) {
        float m = acc[0]; int am = 0;
#pragma unroll
        for (int e = 1; e < NE; e++) if (acc[e] > m) { m = acc[e]; am = e; }
        float p[NE]; float s = 0.f;
#pragma unroll
        for (int e = 0; e < NE; e++) { p[e] = expf(acc[e] - m); s += p[e]; }
        float inv = 1.f / s;
#pragma unroll
        for (int e = 0; e < NE; e++) d_probs[tok * NE + e] = p[e] * inv;
        float z = m + logf(s);
        d_z2[tok] = z * z;
        d_top[tok] = am;
    }
}

// ---------------- 2. ordered capacity scan ----------------
__global__ void scan_kernel()
{
    __shared__ unsigned long long s0[1024], s1[1024];
    __shared__ int base[NE];
    int t = threadIdx.x;
    if (t < NE) base[t] = 0;
    __syncthreads();

    for (int tile = 0; tile < NTOK / 1024; tile++) {
        int i = tile * 1024 + t;
        int e = d_top[i];
        unsigned long long v0 = (e < 4)  ? (1ULL << (16 * e))       : 0ULL;
        unsigned long long v1 = (e >= 4) ? (1ULL << (16 * (e - 4))) : 0ULL;
        s0[t] = v0; s1[t] = v1;
        __syncthreads();
        for (int off = 1; off < 1024; off <<= 1) {
            unsigned long long a0 = (t >= off) ? s0[t - off] : 0ULL;
            unsigned long long a1 = (t >= off) ? s1[t - off] : 0ULL;
            __syncthreads();
            s0[t] += a0; s1[t] += a1;
            __syncthreads();
        }
        unsigned long long w = (e < 4) ? s0[t] : s1[t];
        int sh   = 16 * (e & 3);
        int posl = (int)((w >> sh) & 0xFFFFULL) - 1;
        int pos  = base[e] + posl;
        int kp   = (pos < CAP) ? 1 : 0;
        d_keep[i] = kp;
        if (kp) d_gidx[e * CAP + pos] = i;
        __syncthreads();
        if (t < 4)      base[t] += (int)((s0[1023] >> (16 * t)) & 0xFFFFULL);
        else if (t < 8) base[t] += (int)((s1[1023] >> (16 * (t - 4))) & 0xFFFFULL);
        __syncthreads();
    }
    if (t < NE) {
        d_counts[t] = base[t];
        d_counts_cap[t] = base[t] < CAP ? base[t] : CAP;
    }
}

// ---------------- 3. aux loss ----------------
__global__ void reduce_kernel(float* __restrict__ out_aux)
{
    __shared__ float sm[1024];
    __shared__ float pe[NE];
    int t = threadIdx.x;
    float pp[NE];
#pragma unroll
    for (int e = 0; e < NE; e++) pp[e] = 0.f;
    float zz = 0.f;
    for (int i = t; i < NTOK; i += 1024) {
#pragma unroll
        for (int e = 0; e < NE; e++) pp[e] += d_probs[i * NE + e];
        zz += d_z2[i];
    }
#pragma unroll
    for (int e = 0; e < NE; e++) {
        sm[t] = pp[e]; __syncthreads();
        for (int o = 512; o > 0; o >>= 1) {
            if (t < o) sm[t] += sm[t + o];
            __syncthreads();
        }
        if (t == 0) pe[e] = sm[0];
        __syncthreads();
    }
    sm[t] = zz; __syncthreads();
    for (int o = 512; o > 0; o >>= 1) {
        if (t < o) sm[t] += sm[t + o];
        __syncthreads();
    }
    if (t == 0) {
        float bal = 0.f;
        for (int e = 0; e < NE; e++)
            bal += (pe[e] / (float)NTOK) * ((float)d_counts[e] / (float)NTOK);
        bal *= 0.01f * (float)NE;
        out_aux[0] = bal + (sm[0] / (float)NTOK) * 0.001f;
    }
}

// ---------------- 4/5. fp16 mma.sync GEMMs, ldmatrix + cp.async -----------
// k-tile = 64 halfs (128B rows, SW128), 3-stage pipeline, 2 CTAs/SM.
// MODE 0: h = silu(xe@Wg^T)*(xe@Wu^T)  (A = gathered xh, K=1024, N: 64g+64u)
// MODE 1: out = h@W2^T scattered        (A = d_hh,       K=5632, N-tile 128)
#define STG_B  32768               // bytes per stage (A 16KB + B 16KB)
#define SMEM_G (3 * STG_B)         // 98304 B

template<int MODE>
__global__ __launch_bounds__(256, 2)
void moe_gemm(float* __restrict__ out)
{
    constexpr int KT  = (MODE == 0) ? DDIM / 64 : HDIM / 64;
    constexpr int WNS = (MODE == 0) ? 32 : 64;   // warpN stride (n cols)
    constexpr int NO2 = (MODE == 0) ? 64 : 32;   // row offset of second acc set

    extern __shared__ char smc[];
    __shared__ int s_tok[128];

    const int t = threadIdx.x, wid = t >> 5, lane = t & 31;
    const int lc = lane & 3;
    const int warpM = wid & 3, warpN = wid >> 2;
    const int e = blockIdx.z, m0 = blockIdx.x * 128, nb = blockIdx.y;

    if (t < 128) {
        int cc = d_counts_cap[e];
        s_tok[t] = (m0 + t < cc) ? d_gidx[e * CAP + m0 + t] : ((MODE == 0) ? 0 : -1);
    }
    __syncthreads();

    const uint32_t sbase = smem_u32(smc);
    const int lrow = t >> 1;           // loader row 0..127
    const int q0l  = (t & 1) * 4;      // first of 4 chunks

    auto load_stage = [&](int kt, int s) {
        const uint32_t ab = sbase + (uint32_t)s * STG_B;
        const uint32_t bb = ab + 16384;
        const int k0 = kt * 64;
#pragma unroll
        for (int c = 0; c < 4; c++) {
            int q = q0l + c;
            uint32_t dsw = (uint32_t)(lrow * 128 + ((q ^ (lrow & 7)) << 4));
            const __half* srcA;
            if (MODE == 0)
                srcA = d_xh + (size_t)s_tok[lrow] * DDIM + k0 + q * 8;
            else
                srcA = d_hh + ((size_t)e * CAP + m0 + lrow) * HDIM + k0 + q * 8;
            CP16(ab + dsw, srcA);
            const __half* srcB;
            if (MODE == 0) {
                int wr = (lrow < 64) ? (nb * 64 + lrow)
                                     : (HDIM + nb * 64 + lrow - 64);
                srcB = d_w13h + ((size_t)e * H2 + wr) * DDIM + k0 + q * 8;
            } else {
                srcB = d_w2h + ((size_t)e * DDIM + nb * 128 + lrow) * HDIM + k0 + q * 8;
            }
            CP16(bb + dsw, srcB);
        }
    };

    float c0[2][4][4], c1[2][4][4];
#pragma unroll
    for (int a = 0; a < 2; a++)
#pragma unroll
        for (int b = 0; b < 4; b++)
#pragma unroll
            for (int r = 0; r < 4; r++) { c0[a][b][r] = 0.f; c1[a][b][r] = 0.f; }

    // ldmatrix lane row/chunk mapping (constant per thread)
    const int rA  = warpM * 32 + (lane & 15);        // + mf*16
    const int cselA = lane >> 4;                      // chunk +0/+1
    const int rB  = (lane & 7) + ((lane & 16) >> 1);  // + fragment base
    const int cselB = (lane >> 3) & 1;

    load_stage(0, 0); CPCOMMIT();
    load_stage(1, 1); CPCOMMIT();

    for (int kt = 0; kt < KT; kt++) {
        CPWAIT1();
        __syncthreads();
        if (kt + 2 < KT) load_stage(kt + 2, (kt + 2) % 3);
        CPCOMMIT();

        const uint32_t ab = sbase + (uint32_t)(kt % 3) * STG_B;
        const uint32_t bb = ab + 16384;
#pragma unroll
        for (int kk = 0; kk < 4; kk++) {
            uint32_t a[2][4];
#pragma unroll
            for (int mf = 0; mf < 2; mf++) {
                int r = rA + mf * 16;
                uint32_t ad = ab + r * 128 + (((kk * 2 + cselA) ^ (r & 7)) << 4);
                LDSM4(a[mf][0], a[mf][1], a[mf][2], a[mf][3], ad);
            }
#pragma unroll
            for (int p = 0; p < 2; p++) {
                int r0n = warpN * WNS + p * 16 + rB;
                uint32_t bd0 = bb + r0n * 128 + (((kk * 2 + cselB) ^ (r0n & 7)) << 4);
                uint32_t g0, g1, g2, g3;
                LDSM4(g0, g1, g2, g3, bd0);
                int r1n = r0n + NO2;
                uint32_t bd1 = bb + r1n * 128 + (((kk * 2 + cselB) ^ (r1n & 7)) << 4);
                uint32_t u0, u1, u2, u3;
                LDSM4(u0, u1, u2, u3, bd1);
#pragma unroll
                for (int mf = 0; mf < 2; mf++) {
                    mma_f16(c0[mf][2 * p],     a[mf], g0, g1);
                    mma_f16(c0[mf][2 * p + 1], a[mf], g2, g3);
                    mma_f16(c1[mf][2 * p],     a[mf], u0, u1);
                    mma_f16(c1[mf][2 * p + 1], a[mf], u2, u3);
                }
            }
        }
        __syncthreads();
    }

    const int lr = lane >> 2;
    if (MODE == 0) {
#pragma unroll
        for (int mf = 0; mf < 2; mf++) {
            int r0 = m0 + warpM * 32 + mf * 16 + lr;
#pragma unroll
            for (int nf = 0; nf < 4; nf++) {
                int col = nb * 64 + warpN * 32 + nf * 8 + 2 * lc;
#pragma unroll
                for (int hh = 0; hh < 2; hh++) {
                    float g0 = c0[mf][nf][2 * hh], g1 = c0[mf][nf][2 * hh + 1];
                    float u0 = c1[mf][nf][2 * hh], u1 = c1[mf][nf][2 * hh + 1];
                    float h0 = g0 * u0 / (1.f + expf(-g0));
                    float h1 = g1 * u1 / (1.f + expf(-g1));
                    __half2 hv = __floats2half2_rn(h0, h1);
                    *(__half2*)(d_hh + ((size_t)e * CAP + r0 + 8 * hh) * HDIM + col) = hv;
                }
            }
        }
    } else {
#pragma unroll
        for (int mf = 0; mf < 2; mf++) {
            int rl = warpM * 32 + mf * 16 + lr;
            int tok0 = s_tok[rl], tok1 = s_tok[rl + 8];
#pragma unroll
            for (int nf = 0; nf < 4; nf++) {
                int colA = nb * 128 + warpN * 64 + nf * 8 + 2 * lc;
                int colB = colA + 32;
                if (tok0 >= 0) {
                    *(float2*)(out + (size_t)tok0 * DDIM + colA) =
                        make_float2(c0[mf][nf][0], c0[mf][nf][1]);
                    *(float2*)(out + (size_t)tok0 * DDIM + colB) =
                        make_float2(c1[mf][nf][0], c1[mf][nf][1]);
                }
                if (tok1 >= 0) {
                    *(float2*)(out + (size_t)tok1 * DDIM + colA) =
                        make_float2(c0[mf][nf][2], c0[mf][nf][3]);
                    *(float2*)(out + (size_t)tok1 * DDIM + colB) =
                        make_float2(c1[mf][nf][2], c1[mf][nf][3]);
                }
            }
        }
    }
}

// ---------------- 6. finalize ----------------
__global__ void finalize_kernel(float* __restrict__ out)
{
    int i = blockIdx.x, t = threadIdx.x;
    int kp = d_keep[i];
    if (!kp)
        ((float4*)(out + (size_t)i * DDIM))[t] = make_float4(0.f, 0.f, 0.f, 0.f);
    if (t == 0) {
        out[OUT_TOP + i]  = (float)d_top[i];
        out[OUT_KEEP + i] = kp ? 1.f : 0.f;
    }
}

// ---------------- launch ----------------
extern "C" void kernel_launch(void* const* d_in, const int* in_sizes, int n_in,
                              void* d_out, int out_size)
{
    const float* x   = (const float*)d_in[0];
    const float* Wg  = (const float*)d_in[1];
    const float* W13 = (const float*)d_in[2];
    const float* W2  = (const float*)d_in[3];
    float* out = (float*)d_out;

    cudaFuncSetAttribute(moe_gemm<0>, cudaFuncAttributeMaxDynamicSharedMemorySize, SMEM_G);
    cudaFuncSetAttribute(moe_gemm<1>, cudaFuncAttributeMaxDynamicSharedMemorySize, SMEM_G);

    __half* xh;   cudaGetSymbolAddress((void**)&xh,   d_xh);
    __half* w13h; cudaGetSymbolAddress((void**)&w13h, d_w13h);
    __half* w2h;  cudaGetSymbolAddress((void**)&w2h,  d_w2h);

    const int n4x  = NTOK * DDIM / 4;
    const int n4w1 = NE * H2 * DDIM / 4;
    const int n4w2 = NE * DDIM * HDIM / 4;
    cvt_kernel<<<(n4x  + 255) / 256, 256>>>((const float4*)x,   (uint2*)xh,   n4x);
    cvt_kernel<<<(n4w1 + 255) / 256, 256>>>((const float4*)W13, (uint2*)w13h, n4w1);
    cvt_kernel<<<(n4w2 + 255) / 256, 256>>>((const float4*)W2,  (uint2*)w2h,  n4w2);

    router_kernel<<<NTOK / 8, 256>>>(x, Wg);
    scan_kernel<<<1, 1024>>>();
    reduce_kernel<<<1, 1024>>>(out + OUT_AUX);

    dim3 g1(CAP / 128, HDIM / 64, NE);     // 10 x 88 x 8
    moe_gemm<0><<<g1, 256, SMEM_G>>>(nullptr);

    dim3 g2(CAP / 128, DDIM / 128, NE);    // 10 x 8 x 8
    moe_gemm<1><<<g2, 256, SMEM_G>>>(out);

    finalize_kernel<<<NTOK, 256>>>(out);
}

// round 7
// speedup vs baseline: 10.0422x; 1.3984x over previous
#include <cuda_runtime.h>
#include <cuda_fp16.h>
#include <cstdint>
#include <math.h>

#define NTOK 8192
#define NE   8
#define DDIM 1024
#define HDIM 5632
#define H2   (2*HDIM)
#define CAP  1280

#define OUT_AUX  8388608
#define OUT_TOP  (8388608 + 1)
#define OUT_KEEP (8388608 + 1 + NTOK)

// ---------------- scratch ----------------
__device__ float d_probs[NTOK * NE];
__device__ float d_z2[NTOK];
__device__ int   d_top[NTOK];
__device__ int   d_keep[NTOK];
__device__ int   d_gidx[NE * CAP];
__device__ int   d_counts[NE];
__device__ int   d_counts_cap[NE];
__device__ __align__(256) __half d_hh[(size_t)NE * CAP * HDIM];     // 115 MB
__device__ __align__(256) __half d_xh[(size_t)NTOK * DDIM];         //  17 MB
__device__ __align__(256) __half d_w13h[(size_t)NE * H2 * DDIM];    // 184 MB
__device__ __align__(256) __half d_w2h[(size_t)NE * DDIM * HDIM];   //  92 MB

// ---------------- helpers ----------------
__device__ __forceinline__ uint32_t smem_u32(const void* p) {
    uint32_t a;
    asm("{ .reg .u64 t; cvta.to.shared.u64 t, %1; cvt.u32.u64 %0, t; }"
        : "=r"(a) : "l"(p));
    return a;
}
__device__ __forceinline__ uint32_t h2_u32(__half2 h) {
    return *reinterpret_cast<uint32_t*>(&h);
}
__device__ __forceinline__ void mma_f16(float* c, const uint32_t* a,
                                        uint32_t b0, uint32_t b1) {
    asm volatile(
        "mma.sync.aligned.m16n8k16.row.col.f32.f16.f16.f32 "
        "{%0,%1,%2,%3}, {%4,%5,%6,%7}, {%8,%9}, {%0,%1,%2,%3};"
        : "+f"(c[0]), "+f"(c[1]), "+f"(c[2]), "+f"(c[3])
        : "r"(a[0]), "r"(a[1]), "r"(a[2]), "r"(a[3]), "r"(b0), "r"(b1));
}
#define LDSM4(r0, r1, r2, r3, a) \
    asm volatile("ldmatrix.sync.aligned.m8n8.x4.shared.b16 {%0,%1,%2,%3}, [%4];" \
                 : "=r"(r0), "=r"(r1), "=r"(r2), "=r"(r3) : "r"(a))
#define CP16(d, s) \
    asm volatile("cp.async.cg.shared.global [%0], [%1], 16;" :: "r"(d), "l"(s))
#define CPCOMMIT() asm volatile("cp.async.commit_group;")
#define CPWAIT1()  asm volatile("cp.async.wait_group 1;")

// ---------------- 0. fp32 -> fp16 conversion ----------------
__global__ void cvt_kernel(const float4* __restrict__ src,
                           uint2* __restrict__ dst, int n4)
{
    int i = blockIdx.x * blockDim.x + threadIdx.x;
    if (i < n4) {
        float4 v = src[i];
        __half2 lo = __floats2half2_rn(v.x, v.y);
        __half2 hi = __floats2half2_rn(v.z, v.w);
        dst[i] = make_uint2(h2_u32(lo), h2_u32(hi));
    }
}

// ---------------- 1. router ----------------
__global__ void router_kernel(const float* __restrict__ x,
                              const float* __restrict__ Wg)
{
    __shared__ float sWg[NE * DDIM];
    int t = threadIdx.x;
    for (int i = t; i < NE * DDIM; i += 256) sWg[i] = Wg[i];
    __syncthreads();

    int warp = t >> 5, lane = t & 31;
    int tok  = blockIdx.x * 8 + warp;
    const float* xr = x + (size_t)tok * DDIM;

    float acc[NE];
#pragma unroll
    for (int e = 0; e < NE; e++) acc[e] = 0.f;
    for (int k = lane; k < DDIM; k += 32) {
        float xv = xr[k];
#pragma unroll
        for (int e = 0; e < NE; e++) acc[e] = fmaf(xv, sWg[e * DDIM + k], acc[e]);
    }
#pragma unroll
    for (int e = 0; e < NE; e++) {
#pragma unroll
        for (int o = 16; o > 0; o >>= 1)
            acc[e] += __shfl_down_sync(0xffffffffu, acc[e], o);
    }
    if (lane == 0) {
        float m = acc[0]; int am = 0;
#pragma unroll
        for (int e = 1; e < NE; e++) if (acc[e] > m) { m = acc[e]; am = e; }
        float p[NE]; float s = 0.f;
#pragma unroll
        for (int e = 0; e < NE; e++) { p[e] = expf(acc[e] - m); s += p[e]; }
        float inv = 1.f / s;
#pragma unroll
        for (int e = 0; e < NE; e++) d_probs[tok * NE + e] = p[e] * inv;
        float z = m + logf(s);
        d_z2[tok] = z * z;
        d_top[tok] = am;
    }
}

// ---------------- 2. ordered capacity scan (shfl-based) ----------------
__global__ void scan_kernel()
{
    __shared__ unsigned long long wsum0[32], wsum1[32];
    __shared__ unsigned long long tile0, tile1;
    __shared__ int base[NE];
    const int t = threadIdx.x, lane = t & 31, wid = t >> 5;
    if (t < NE) base[t] = 0;
    __syncthreads();

    for (int tile = 0; tile < NTOK / 1024; tile++) {
        int i = tile * 1024 + t;
        int e = d_top[i];
        unsigned long long v0 = (e < 4)  ? (1ULL << (16 * e))       : 0ULL;
        unsigned long long v1 = (e >= 4) ? (1ULL << (16 * (e - 4))) : 0ULL;
        unsigned long long s0 = v0, s1 = v1;
#pragma unroll
        for (int o = 1; o < 32; o <<= 1) {
            unsigned long long a0 = __shfl_up_sync(0xffffffffu, s0, o);
            unsigned long long a1 = __shfl_up_sync(0xffffffffu, s1, o);
            if (lane >= o) { s0 += a0; s1 += a1; }
        }
        if (lane == 31) { wsum0[wid] = s0; wsum1[wid] = s1; }
        __syncthreads();
        if (wid == 0) {
            unsigned long long w0 = wsum0[lane], w1 = wsum1[lane];
            unsigned long long p0 = w0, p1 = w1;
#pragma unroll
            for (int o = 1; o < 32; o <<= 1) {
                unsigned long long a0 = __shfl_up_sync(0xffffffffu, p0, o);
                unsigned long long a1 = __shfl_up_sync(0xffffffffu, p1, o);
                if (lane >= o) { p0 += a0; p1 += a1; }
            }
            wsum0[lane] = p0 - w0;       // exclusive warp offsets
            wsum1[lane] = p1 - w1;
            if (lane == 31) { tile0 = p0; tile1 = p1; }
        }
        __syncthreads();
        unsigned long long inc = (e < 4) ? (s0 + wsum0[wid]) : (s1 + wsum1[wid]);
        int sh  = 16 * (e & 3);
        int pos = base[e] + (int)((inc >> sh) & 0xFFFFULL) - 1;
        int kp  = (pos < CAP) ? 1 : 0;
        d_keep[i] = kp;
        if (kp) d_gidx[e * CAP + pos] = i;
        __syncthreads();
        if (t < 4)      base[t] += (int)((tile0 >> (16 * t)) & 0xFFFFULL);
        else if (t < 8) base[t] += (int)((tile1 >> (16 * (t - 4))) & 0xFFFFULL);
        __syncthreads();
    }
    if (t < NE) {
        d_counts[t] = base[t];
        d_counts_cap[t] = base[t] < CAP ? base[t] : CAP;
    }
}

// ---------------- 3. aux loss ----------------
__global__ void reduce_kernel(float* __restrict__ out_aux)
{
    __shared__ float sm[1024];
    __shared__ float pe[NE];
    int t = threadIdx.x;
    float pp[NE];
#pragma unroll
    for (int e = 0; e < NE; e++) pp[e] = 0.f;
    float zz = 0.f;
    for (int i = t; i < NTOK; i += 1024) {
#pragma unroll
        for (int e = 0; e < NE; e++) pp[e] += d_probs[i * NE + e];
        zz += d_z2[i];
    }
#pragma unroll
    for (int e = 0; e < NE; e++) {
        sm[t] = pp[e]; __syncthreads();
        for (int o = 512; o > 0; o >>= 1) {
            if (t < o) sm[t] += sm[t + o];
            __syncthreads();
        }
        if (t == 0) pe[e] = sm[0];
        __syncthreads();
    }
    sm[t] = zz; __syncthreads();
    for (int o = 512; o > 0; o >>= 1) {
        if (t < o) sm[t] += sm[t + o];
        __syncthreads();
    }
    if (t == 0) {
        float bal = 0.f;
        for (int e = 0; e < NE; e++)
            bal += (pe[e] / (float)NTOK) * ((float)d_counts[e] / (float)NTOK);
        bal *= 0.01f * (float)NE;
        out_aux[0] = bal + (sm[0] / (float)NTOK) * 0.001f;
    }
}

// ---------------- 4/5. fp16 mma.sync GEMMs, ldmatrix + cp.async -----------
// k-tile = 64 halfs (128B rows, SW128), 3-stage pipeline, 2 CTAs/SM.
// MODE 0: h = silu(xe@Wg^T)*(xe@Wu^T)  (A = gathered xh, K=1024, N: 64g+64u)
// MODE 1: out = h@W2^T scattered        (A = d_hh,       K=5632, N-tile 128)
// Blocks whose whole M-range is beyond the expert's kept-token count exit
// immediately: their outputs are provably never read.
#define STG_B  32768               // bytes per stage (A 16KB + B 16KB)
#define SMEM_G (3 * STG_B)         // 98304 B

template<int MODE>
__global__ __launch_bounds__(256, 2)
void moe_gemm(float* __restrict__ out)
{
    constexpr int KT  = (MODE == 0) ? DDIM / 64 : HDIM / 64;
    constexpr int WNS = (MODE == 0) ? 32 : 64;   // warpN stride (n cols)
    constexpr int NO2 = (MODE == 0) ? 64 : 32;   // row offset of second acc set

    extern __shared__ char smc[];
    __shared__ int s_tok[128];

    const int t = threadIdx.x, wid = t >> 5, lane = t & 31;
    const int lc = lane & 3;
    const int warpM = wid & 3, warpN = wid >> 2;
    const int e = blockIdx.z, m0 = blockIdx.x * 128, nb = blockIdx.y;

    const int cc = d_counts_cap[e];
    if (m0 >= cc) return;            // dead capacity rows: outputs never read

    if (t < 128)
        s_tok[t] = (m0 + t < cc) ? d_gidx[e * CAP + m0 + t] : ((MODE == 0) ? 0 : -1);
    __syncthreads();

    const uint32_t sbase = smem_u32(smc);
    const int lrow = t >> 1;           // loader row 0..127
    const int q0l  = (t & 1) * 4;      // first of 4 chunks

    auto load_stage = [&](int kt, int s) {
        const uint32_t ab = sbase + (uint32_t)s * STG_B;
        const uint32_t bb = ab + 16384;
        const int k0 = kt * 64;
#pragma unroll
        for (int c = 0; c < 4; c++) {
            int q = q0l + c;
            uint32_t dsw = (uint32_t)(lrow * 128 + ((q ^ (lrow & 7)) << 4));
            const __half* srcA;
            if (MODE == 0)
                srcA = d_xh + (size_t)s_tok[lrow] * DDIM + k0 + q * 8;
            else
                srcA = d_hh + ((size_t)e * CAP + m0 + lrow) * HDIM + k0 + q * 8;
            CP16(ab + dsw, srcA);
            const __half* srcB;
            if (MODE == 0) {
                int wr = (lrow < 64) ? (nb * 64 + lrow)
                                     : (HDIM + nb * 64 + lrow - 64);
                srcB = d_w13h + ((size_t)e * H2 + wr) * DDIM + k0 + q * 8;
            } else {
                srcB = d_w2h + ((size_t)e * DDIM + nb * 128 + lrow) * HDIM + k0 + q * 8;
            }
            CP16(bb + dsw, srcB);
        }
    };

    float c0[2][4][4], c1[2][4][4];
#pragma unroll
    for (int a = 0; a < 2; a++)
#pragma unroll
        for (int b = 0; b < 4; b++)
#pragma unroll
            for (int r = 0; r < 4; r++) { c0[a][b][r] = 0.f; c1[a][b][r] = 0.f; }

    // ldmatrix lane row/chunk mapping (constant per thread)
    const int rA  = warpM * 32 + (lane & 15);        // + mf*16
    const int cselA = lane >> 4;                      // chunk +0/+1
    const int rB  = (lane & 7) + ((lane & 16) >> 1);  // + fragment base
    const int cselB = (lane >> 3) & 1;

    load_stage(0, 0); CPCOMMIT();
    load_stage(1, 1); CPCOMMIT();

    for (int kt = 0; kt < KT; kt++) {
        CPWAIT1();
        __syncthreads();
        if (kt + 2 < KT) load_stage(kt + 2, (kt + 2) % 3);
        CPCOMMIT();

        const uint32_t ab = sbase + (uint32_t)(kt % 3) * STG_B;
        const uint32_t bb = ab + 16384;
#pragma unroll
        for (int kk = 0; kk < 4; kk++) {
            uint32_t a[2][4];
#pragma unroll
            for (int mf = 0; mf < 2; mf++) {
                int r = rA + mf * 16;
                uint32_t ad = ab + r * 128 + (((kk * 2 + cselA) ^ (r & 7)) << 4);
                LDSM4(a[mf][0], a[mf][1], a[mf][2], a[mf][3], ad);
            }
#pragma unroll
            for (int p = 0; p < 2; p++) {
                int r0n = warpN * WNS + p * 16 + rB;
                uint32_t bd0 = bb + r0n * 128 + (((kk * 2 + cselB) ^ (r0n & 7)) << 4);
                uint32_t g0, g1, g2, g3;
                LDSM4(g0, g1, g2, g3, bd0);
                int r1n = r0n + NO2;
                uint32_t bd1 = bb + r1n * 128 + (((kk * 2 + cselB) ^ (r1n & 7)) << 4);
                uint32_t u0, u1, u2, u3;
                LDSM4(u0, u1, u2, u3, bd1);
#pragma unroll
                for (int mf = 0; mf < 2; mf++) {
                    mma_f16(c0[mf][2 * p],     a[mf], g0, g1);
                    mma_f16(c0[mf][2 * p + 1], a[mf], g2, g3);
                    mma_f16(c1[mf][2 * p],     a[mf], u0, u1);
                    mma_f16(c1[mf][2 * p + 1], a[mf], u2, u3);
                }
            }
        }
        __syncthreads();
    }

    const int lr = lane >> 2;
    if (MODE == 0) {
#pragma unroll
        for (int mf = 0; mf < 2; mf++) {
            int r0 = m0 + warpM * 32 + mf * 16 + lr;
#pragma unroll
            for (int nf = 0; nf < 4; nf++) {
                int col = nb * 64 + warpN * 32 + nf * 8 + 2 * lc;
#pragma unroll
                for (int hh = 0; hh < 2; hh++) {
                    float g0 = c0[mf][nf][2 * hh], g1 = c0[mf][nf][2 * hh + 1];
                    float u0 = c1[mf][nf][2 * hh], u1 = c1[mf][nf][2 * hh + 1];
                    float h0 = g0 * u0 / (1.f + expf(-g0));
                    float h1 = g1 * u1 / (1.f + expf(-g1));
                    __half2 hv = __floats2half2_rn(h0, h1);
                    *(__half2*)(d_hh + ((size_t)e * CAP + r0 + 8 * hh) * HDIM + col) = hv;
                }
            }
        }
    } else {
#pragma unroll
        for (int mf = 0; mf < 2; mf++) {
            int rl = warpM * 32 + mf * 16 + lr;
            int tok0 = s_tok[rl], tok1 = s_tok[rl + 8];
#pragma unroll
            for (int nf = 0; nf < 4; nf++) {
                int colA = nb * 128 + warpN * 64 + nf * 8 + 2 * lc;
                int colB = colA + 32;
                if (tok0 >= 0) {
                    *(float2*)(out + (size_t)tok0 * DDIM + colA) =
                        make_float2(c0[mf][nf][0], c0[mf][nf][1]);
                    *(float2*)(out + (size_t)tok0 * DDIM + colB) =
                        make_float2(c1[mf][nf][0], c1[mf][nf][1]);
                }
                if (tok1 >= 0) {
                    *(float2*)(out + (size_t)tok1 * DDIM + colA) =
                        make_float2(c0[mf][nf][2], c0[mf][nf][3]);
                    *(float2*)(out + (size_t)tok1 * DDIM + colB) =
                        make_float2(c1[mf][nf][2], c1[mf][nf][3]);
                }
            }
        }
    }
}

// ---------------- 6. finalize ----------------
__global__ void finalize_kernel(float* __restrict__ out)
{
    int i = blockIdx.x, t = threadIdx.x;
    int kp = d_keep[i];
    if (!kp)
        ((float4*)(out + (size_t)i * DDIM))[t] = make_float4(0.f, 0.f, 0.f, 0.f);
    if (t == 0) {
        out[OUT_TOP + i]  = (float)d_top[i];
        out[OUT_KEEP + i] = kp ? 1.f : 0.f;
    }
}

// ---------------- launch ----------------
extern "C" void kernel_launch(void* const* d_in, const int* in_sizes, int n_in,
                              void* d_out, int out_size)
{
    const float* x   = (const float*)d_in[0];
    const float* Wg  = (const float*)d_in[1];
    const float* W13 = (const float*)d_in[2];
    const float* W2  = (const float*)d_in[3];
    float* out = (float*)d_out;

    cudaFuncSetAttribute(moe_gemm<0>, cudaFuncAttributeMaxDynamicSharedMemorySize, SMEM_G);
    cudaFuncSetAttribute(moe_gemm<1>, cudaFuncAttributeMaxDynamicSharedMemorySize, SMEM_G);

    __half* xh;   cudaGetSymbolAddress((void**)&xh,   d_xh);
    __half* w13h; cudaGetSymbolAddress((void**)&w13h, d_w13h);
    __half* w2h;  cudaGetSymbolAddress((void**)&w2h,  d_w2h);

    const int n4x  = NTOK * DDIM / 4;
    const int n4w1 = NE * H2 * DDIM / 4;
    const int n4w2 = NE * DDIM * HDIM / 4;
    cvt_kernel<<<(n4x  + 255) / 256, 256>>>((const float4*)x,   (uint2*)xh,   n4x);
    cvt_kernel<<<(n4w1 + 255) / 256, 256>>>((const float4*)W13, (uint2*)w13h, n4w1);
    cvt_kernel<<<(n4w2 + 255) / 256, 256>>>((const float4*)W2,  (uint2*)w2h,  n4w2);

    router_kernel<<<NTOK / 8, 256>>>(x, Wg);
    scan_kernel<<<1, 1024>>>();
    reduce_kernel<<<1, 1024>>>(out + OUT_AUX);

    dim3 g1(CAP / 128, HDIM / 64, NE);     // 10 x 88 x 8
    moe_gemm<0><<<g1, 256, SMEM_G>>>(nullptr);

    dim3 g2(CAP / 128, DDIM / 128, NE);    // 10 x 8 x 8
    moe_gemm<1><<<g2, 256, SMEM_G>>>(out);

    finalize_kernel<<<NTOK, 256>>>(out);
}

// round 8
// speedup vs baseline: 10.3749x; 1.0331x over previous
#include <cuda_runtime.h>
#include <cuda_fp16.h>
#include <cstdint>
#include <math.h>

#define NTOK 8192
#define NE   8
#define DDIM 1024
#define HDIM 5632
#define H2   (2*HDIM)
#define CAP  1280

#define OUT_AUX  8388608
#define OUT_TOP  (8388608 + 1)
#define OUT_KEEP (8388608 + 1 + NTOK)

// ---------------- scratch ----------------
__device__ float d_probs[NTOK * NE];
__device__ float d_z2[NTOK];
__device__ int   d_top[NTOK];
__device__ int   d_keep[NTOK];
__device__ int   d_gidx[NE * CAP];
__device__ int   d_counts[NE];
__device__ int   d_counts_cap[NE];
__device__ __align__(256) __half d_hh[(size_t)NE * CAP * HDIM];     // 115 MB
__device__ __align__(256) __half d_xh[(size_t)NTOK * DDIM];         //  17 MB
__device__ __align__(256) __half d_w13h[(size_t)NE * H2 * DDIM];    // 184 MB
__device__ __align__(256) __half d_w2h[(size_t)NE * DDIM * HDIM];   //  92 MB

// ---------------- helpers ----------------
__device__ __forceinline__ uint32_t smem_u32(const void* p) {
    uint32_t a;
    asm("{ .reg .u64 t; cvta.to.shared.u64 t, %1; cvt.u32.u64 %0, t; }"
        : "=r"(a) : "l"(p));
    return a;
}
__device__ __forceinline__ uint32_t h2_u32(__half2 h) {
    return *reinterpret_cast<uint32_t*>(&h);
}
__device__ __forceinline__ void mma_f16(float* c, const uint32_t* a,
                                        uint32_t b0, uint32_t b1) {
    asm volatile(
        "mma.sync.aligned.m16n8k16.row.col.f32.f16.f16.f32 "
        "{%0,%1,%2,%3}, {%4,%5,%6,%7}, {%8,%9}, {%0,%1,%2,%3};"
        : "+f"(c[0]), "+f"(c[1]), "+f"(c[2]), "+f"(c[3])
        : "r"(a[0]), "r"(a[1]), "r"(a[2]), "r"(a[3]), "r"(b0), "r"(b1));
}
#define LDSM4(r0, r1, r2, r3, a) \
    asm volatile("ldmatrix.sync.aligned.m8n8.x4.shared.b16 {%0,%1,%2,%3}, [%4];" \
                 : "=r"(r0), "=r"(r1), "=r"(r2), "=r"(r3) : "r"(a))
#define CP16(d, s) \
    asm volatile("cp.async.cg.shared.global [%0], [%1], 16;" :: "r"(d), "l"(s))
#define CPCOMMIT() asm volatile("cp.async.commit_group;")
#define CPWAIT1()  asm volatile("cp.async.wait_group 1;")

// ---------------- 0. fp32 -> fp16 conversion ----------------
__global__ void cvt_kernel(const float4* __restrict__ src,
                           uint2* __restrict__ dst, int n4)
{
    int i = blockIdx.x * blockDim.x + threadIdx.x;
    if (i < n4) {
        float4 v = src[i];
        __half2 lo = __floats2half2_rn(v.x, v.y);
        __half2 hi = __floats2half2_rn(v.z, v.w);
        dst[i] = make_uint2(h2_u32(lo), h2_u32(hi));
    }
}

// ---------------- 1. router ----------------
__global__ void router_kernel(const float* __restrict__ x,
                              const float* __restrict__ Wg)
{
    __shared__ float sWg[NE * DDIM];
    int t = threadIdx.x;
    for (int i = t; i < NE * DDIM; i += 256) sWg[i] = Wg[i];
    __syncthreads();

    int warp = t >> 5, lane = t & 31;
    int tok  = blockIdx.x * 8 + warp;
    const float* xr = x + (size_t)tok * DDIM;

    float acc[NE];
#pragma unroll
    for (int e = 0; e < NE; e++) acc[e] = 0.f;
    for (int k = lane; k < DDIM; k += 32) {
        float xv = xr[k];
#pragma unroll
        for (int e = 0; e < NE; e++) acc[e] = fmaf(xv, sWg[e * DDIM + k], acc[e]);
    }
#pragma unroll
    for (int e = 0; e < NE; e++) {
#pragma unroll
        for (int o = 16; o > 0; o >>= 1)
            acc[e] += __shfl_down_sync(0xffffffffu, acc[e], o);
    }
    if (lane == 0) {
        float m = acc[0]; int am = 0;
#pragma unroll
        for (int e = 1; e < NE; e++) if (acc[e] > m) { m = acc[e]; am = e; }
        float p[NE]; float s = 0.f;
#pragma unroll
        for (int e = 0; e < NE; e++) { p[e] = expf(acc[e] - m); s += p[e]; }
        float inv = 1.f / s;
#pragma unroll
        for (int e = 0; e < NE; e++) d_probs[tok * NE + e] = p[e] * inv;
        float z = m + logf(s);
        d_z2[tok] = z * z;
        d_top[tok] = am;
    }
}

// ---------------- 2. ordered capacity scan (shfl-based) ----------------
__global__ void scan_kernel()
{
    __shared__ unsigned long long wsum0[32], wsum1[32];
    __shared__ unsigned long long tile0, tile1;
    __shared__ int base[NE];
    const int t = threadIdx.x, lane = t & 31, wid = t >> 5;
    if (t < NE) base[t] = 0;
    __syncthreads();

    for (int tile = 0; tile < NTOK / 1024; tile++) {
        int i = tile * 1024 + t;
        int e = d_top[i];
        unsigned long long v0 = (e < 4)  ? (1ULL << (16 * e))       : 0ULL;
        unsigned long long v1 = (e >= 4) ? (1ULL << (16 * (e - 4))) : 0ULL;
        unsigned long long s0 = v0, s1 = v1;
#pragma unroll
        for (int o = 1; o < 32; o <<= 1) {
            unsigned long long a0 = __shfl_up_sync(0xffffffffu, s0, o);
            unsigned long long a1 = __shfl_up_sync(0xffffffffu, s1, o);
            if (lane >= o) { s0 += a0; s1 += a1; }
        }
        if (lane == 31) { wsum0[wid] = s0; wsum1[wid] = s1; }
        __syncthreads();
        if (wid == 0) {
            unsigned long long w0 = wsum0[lane], w1 = wsum1[lane];
            unsigned long long p0 = w0, p1 = w1;
#pragma unroll
            for (int o = 1; o < 32; o <<= 1) {
                unsigned long long a0 = __shfl_up_sync(0xffffffffu, p0, o);
                unsigned long long a1 = __shfl_up_sync(0xffffffffu, p1, o);
                if (lane >= o) { p0 += a0; p1 += a1; }
            }
            wsum0[lane] = p0 - w0;       // exclusive warp offsets
            wsum1[lane] = p1 - w1;
            if (lane == 31) { tile0 = p0; tile1 = p1; }
        }
        __syncthreads();
        unsigned long long inc = (e < 4) ? (s0 + wsum0[wid]) : (s1 + wsum1[wid]);
        int sh  = 16 * (e & 3);
        int pos = base[e] + (int)((inc >> sh) & 0xFFFFULL) - 1;
        int kp  = (pos < CAP) ? 1 : 0;
        d_keep[i] = kp;
        if (kp) d_gidx[e * CAP + pos] = i;
        __syncthreads();
        if (t < 4)      base[t] += (int)((tile0 >> (16 * t)) & 0xFFFFULL);
        else if (t < 8) base[t] += (int)((tile1 >> (16 * (t - 4))) & 0xFFFFULL);
        __syncthreads();
    }
    if (t < NE) {
        d_counts[t] = base[t];
        d_counts_cap[t] = base[t] < CAP ? base[t] : CAP;
    }
}

// ---------------- 3. aux loss ----------------
__global__ void reduce_kernel(float* __restrict__ out_aux)
{
    __shared__ float sm[1024];
    __shared__ float pe[NE];
    int t = threadIdx.x;
    float pp[NE];
#pragma unroll
    for (int e = 0; e < NE; e++) pp[e] = 0.f;
    float zz = 0.f;
    for (int i = t; i < NTOK; i += 1024) {
#pragma unroll
        for (int e = 0; e < NE; e++) pp[e] += d_probs[i * NE + e];
        zz += d_z2[i];
    }
#pragma unroll
    for (int e = 0; e < NE; e++) {
        sm[t] = pp[e]; __syncthreads();
        for (int o = 512; o > 0; o >>= 1) {
            if (t < o) sm[t] += sm[t + o];
            __syncthreads();
        }
        if (t == 0) pe[e] = sm[0];
        __syncthreads();
    }
    sm[t] = zz; __syncthreads();
    for (int o = 512; o > 0; o >>= 1) {
        if (t < o) sm[t] += sm[t + o];
        __syncthreads();
    }
    if (t == 0) {
        float bal = 0.f;
        for (int e = 0; e < NE; e++)
            bal += (pe[e] / (float)NTOK) * ((float)d_counts[e] / (float)NTOK);
        bal *= 0.01f * (float)NE;
        out_aux[0] = bal + (sm[0] / (float)NTOK) * 0.001f;
    }
}

// ---------------- 4/5. fp16 mma.sync GEMMs, ldmatrix + cp.async -----------
#define STG_B  32768               // bytes per stage (A 16KB + B 16KB)
#define SMEM_G (3 * STG_B)         // 98304 B

template<int MODE>
__global__ __launch_bounds__(256, 2)
void moe_gemm(float* __restrict__ out)
{
    constexpr int KT  = (MODE == 0) ? DDIM / 64 : HDIM / 64;
    constexpr int WNS = (MODE == 0) ? 32 : 64;   // warpN stride (n cols)
    constexpr int NO2 = (MODE == 0) ? 64 : 32;   // row offset of second acc set

    extern __shared__ char smc[];
    __shared__ int s_tok[128];

    const int t = threadIdx.x, wid = t >> 5, lane = t & 31;
    const int lc = lane & 3;
    const int warpM = wid & 3, warpN = wid >> 2;
    const int e = blockIdx.z, m0 = blockIdx.x * 128, nb = blockIdx.y;

    const int cc = d_counts_cap[e];
    if (m0 >= cc) return;            // dead capacity rows: outputs never read

    if (t < 128)
        s_tok[t] = (m0 + t < cc) ? d_gidx[e * CAP + m0 + t] : ((MODE == 0) ? 0 : -1);
    __syncthreads();

    const uint32_t sbase = smem_u32(smc);
    const int lrow = t >> 1;           // loader row 0..127
    const int q0l  = (t & 1) * 4;      // first of 4 chunks

    auto load_stage = [&](int kt, int s) {
        const uint32_t ab = sbase + (uint32_t)s * STG_B;
        const uint32_t bb = ab + 16384;
        const int k0 = kt * 64;
#pragma unroll
        for (int c = 0; c < 4; c++) {
            int q = q0l + c;
            uint32_t dsw = (uint32_t)(lrow * 128 + ((q ^ (lrow & 7)) << 4));
            const __half* srcA;
            if (MODE == 0)
                srcA = d_xh + (size_t)s_tok[lrow] * DDIM + k0 + q * 8;
            else
                srcA = d_hh + ((size_t)e * CAP + m0 + lrow) * HDIM + k0 + q * 8;
            CP16(ab + dsw, srcA);
            const __half* srcB;
            if (MODE == 0) {
                int wr = (lrow < 64) ? (nb * 64 + lrow)
                                     : (HDIM + nb * 64 + lrow - 64);
                srcB = d_w13h + ((size_t)e * H2 + wr) * DDIM + k0 + q * 8;
            } else {
                srcB = d_w2h + ((size_t)e * DDIM + nb * 128 + lrow) * HDIM + k0 + q * 8;
            }
            CP16(bb + dsw, srcB);
        }
    };

    float c0[2][4][4], c1[2][4][4];
#pragma unroll
    for (int a = 0; a < 2; a++)
#pragma unroll
        for (int b = 0; b < 4; b++)
#pragma unroll
            for (int r = 0; r < 4; r++) { c0[a][b][r] = 0.f; c1[a][b][r] = 0.f; }

    const int rA  = warpM * 32 + (lane & 15);        // + mf*16
    const int cselA = lane >> 4;
    const int rB  = (lane & 7) + ((lane & 16) >> 1);
    const int cselB = (lane >> 3) & 1;

    load_stage(0, 0); CPCOMMIT();
    load_stage(1, 1); CPCOMMIT();

    for (int kt = 0; kt < KT; kt++) {
        CPWAIT1();
        __syncthreads();
        if (kt + 2 < KT) load_stage(kt + 2, (kt + 2) % 3);
        CPCOMMIT();

        const uint32_t ab = sbase + (uint32_t)(kt % 3) * STG_B;
        const uint32_t bb = ab + 16384;
#pragma unroll
        for (int kk = 0; kk < 4; kk++) {
            uint32_t a[2][4];
#pragma unroll
            for (int mf = 0; mf < 2; mf++) {
                int r = rA + mf * 16;
                uint32_t ad = ab + r * 128 + (((kk * 2 + cselA) ^ (r & 7)) << 4);
                LDSM4(a[mf][0], a[mf][1], a[mf][2], a[mf][3], ad);
            }
#pragma unroll
            for (int p = 0; p < 2; p++) {
                int r0n = warpN * WNS + p * 16 + rB;
                uint32_t bd0 = bb + r0n * 128 + (((kk * 2 + cselB) ^ (r0n & 7)) << 4);
                uint32_t g0, g1, g2, g3;
                LDSM4(g0, g1, g2, g3, bd0);
                int r1n = r0n + NO2;
                uint32_t bd1 = bb + r1n * 128 + (((kk * 2 + cselB) ^ (r1n & 7)) << 4);
                uint32_t u0, u1, u2, u3;
                LDSM4(u0, u1, u2, u3, bd1);
#pragma unroll
                for (int mf = 0; mf < 2; mf++) {
                    mma_f16(c0[mf][2 * p],     a[mf], g0, g1);
                    mma_f16(c0[mf][2 * p + 1], a[mf], g2, g3);
                    mma_f16(c1[mf][2 * p],     a[mf], u0, u1);
                    mma_f16(c1[mf][2 * p + 1], a[mf], u2, u3);
                }
            }
        }
        __syncthreads();
    }

    const int lr = lane >> 2;
    if (MODE == 0) {
#pragma unroll
        for (int mf = 0; mf < 2; mf++) {
            int r0 = m0 + warpM * 32 + mf * 16 + lr;
#pragma unroll
            for (int nf = 0; nf < 4; nf++) {
                int col = nb * 64 + warpN * 32 + nf * 8 + 2 * lc;
#pragma unroll
                for (int hh = 0; hh < 2; hh++) {
                    float g0 = c0[mf][nf][2 * hh], g1 = c0[mf][nf][2 * hh + 1];
                    float u0 = c1[mf][nf][2 * hh], u1 = c1[mf][nf][2 * hh + 1];
                    float h0 = g0 * u0 / (1.f + expf(-g0));
                    float h1 = g1 * u1 / (1.f + expf(-g1));
                    __half2 hv = __floats2half2_rn(h0, h1);
                    *(__half2*)(d_hh + ((size_t)e * CAP + r0 + 8 * hh) * HDIM + col) = hv;
                }
            }
        }
    } else {
#pragma unroll
        for (int mf = 0; mf < 2; mf++) {
            int rl = warpM * 32 + mf * 16 + lr;
            int tok0 = s_tok[rl], tok1 = s_tok[rl + 8];
#pragma unroll
            for (int nf = 0; nf < 4; nf++) {
                int colA = nb * 128 + warpN * 64 + nf * 8 + 2 * lc;
                int colB = colA + 32;
                if (tok0 >= 0) {
                    *(float2*)(out + (size_t)tok0 * DDIM + colA) =
                        make_float2(c0[mf][nf][0], c0[mf][nf][1]);
                    *(float2*)(out + (size_t)tok0 * DDIM + colB) =
                        make_float2(c1[mf][nf][0], c1[mf][nf][1]);
                }
                if (tok1 >= 0) {
                    *(float2*)(out + (size_t)tok1 * DDIM + colA) =
                        make_float2(c0[mf][nf][2], c0[mf][nf][3]);
                    *(float2*)(out + (size_t)tok1 * DDIM + colB) =
                        make_float2(c1[mf][nf][2], c1[mf][nf][3]);
                }
            }
        }
    }
}

// ---------------- 6. finalize (independent of GEMMs for dropped rows) ------
__global__ void finalize_kernel(float* __restrict__ out)
{
    int i = blockIdx.x, t = threadIdx.x;
    int kp = d_keep[i];
    if (!kp)
        ((float4*)(out + (size_t)i * DDIM))[t] = make_float4(0.f, 0.f, 0.f, 0.f);
    if (t == 0) {
        out[OUT_TOP + i]  = (float)d_top[i];
        out[OUT_KEEP + i] = kp ? 1.f : 0.f;
    }
}

// ---------------- launch: two-stream captured DAG ---------------------------
extern "C" void kernel_launch(void* const* d_in, const int* in_sizes, int n_in,
                              void* d_out, int out_size)
{
    const float* x   = (const float*)d_in[0];
    const float* Wg  = (const float*)d_in[1];
    const float* W13 = (const float*)d_in[2];
    const float* W2  = (const float*)d_in[3];
    float* out = (float*)d_out;

    cudaFuncSetAttribute(moe_gemm<0>, cudaFuncAttributeMaxDynamicSharedMemorySize, SMEM_G);
    cudaFuncSetAttribute(moe_gemm<1>, cudaFuncAttributeMaxDynamicSharedMemorySize, SMEM_G);

    __half* xh;   cudaGetSymbolAddress((void**)&xh,   d_xh);
    __half* w13h; cudaGetSymbolAddress((void**)&w13h, d_w13h);
    __half* w2h;  cudaGetSymbolAddress((void**)&w2h,  d_w2h);

    const int n4x  = NTOK * DDIM / 4;
    const int n4w1 = NE * H2 * DDIM / 4;
    const int n4w2 = NE * DDIM * HDIM / 4;

    cudaStream_t s2;
    cudaEvent_t evFork, evJoin1, evJoin2;
    cudaStreamCreateWithFlags(&s2, cudaStreamNonBlocking);
    cudaEventCreateWithFlags(&evFork,  cudaEventDisableTiming);
    cudaEventCreateWithFlags(&evJoin1, cudaEventDisableTiming);
    cudaEventCreateWithFlags(&evJoin2, cudaEventDisableTiming);

    // fork
    cudaEventRecord(evFork, 0);
    cudaStreamWaitEvent(s2, evFork, 0);

    // side stream: token path + small kernels + W2 conversion
    cvt_kernel<<<(n4x + 255) / 256, 256, 0, s2>>>((const float4*)x, (uint2*)xh, n4x);
    router_kernel<<<NTOK / 8, 256, 0, s2>>>(x, Wg);
    scan_kernel<<<1, 1024, 0, s2>>>();
    cudaEventRecord(evJoin1, s2);               // gemm1 deps: xh + gidx/counts
    reduce_kernel<<<1, 1024, 0, s2>>>(out + OUT_AUX);
    finalize_kernel<<<NTOK, 256, 0, s2>>>(out); // zeros dropped rows, top/keep
    cvt_kernel<<<(n4w2 + 255) / 256, 256, 0, s2>>>((const float4*)W2, (uint2*)w2h, n4w2);
    cudaEventRecord(evJoin2, s2);               // gemm2 deps: w2h (+ ordering)

    // main stream: W13 conversion runs concurrent with side stream
    cvt_kernel<<<(n4w1 + 255) / 256, 256>>>((const float4*)W13, (uint2*)w13h, n4w1);

    cudaStreamWaitEvent(0, evJoin1, 0);
    dim3 g1(CAP / 128, HDIM / 64, NE);     // 10 x 88 x 8
    moe_gemm<0><<<g1, 256, SMEM_G>>>(nullptr);

    cudaStreamWaitEvent(0, evJoin2, 0);
    dim3 g2(CAP / 128, DDIM / 128, NE);    // 10 x 8 x 8
    moe_gemm<1><<<g2, 256, SMEM_G>>>(out);

    cudaEventDestroy(evFork);
    cudaEventDestroy(evJoin1);
    cudaEventDestroy(evJoin2);
    cudaStreamDestroy(s2);
}